// round 13
// baseline (speedup 1.0000x reference)
#include <cuda_runtime.h>
#include <cuda_fp16.h>
#include <math.h>

#define EPSV 1e-5f

constexpr int C   = 128;
constexpr int CH  = 256;   // C*H
constexpr int KK  = 27;
constexpr int MM  = 2;
constexpr int NPTS = 131072;
constexpr int NSB = 512;   // q stat partial blocks

// ---------------- device scratch (static; no allocations allowed) --------------
__device__ __half g_vh [(size_t)NPTS * CH];   // x @ Wv (pre-BN), fp16
__device__ __half g_vr [(size_t)NPTS * CH];   // relu(bn(v)), fp16
__device__ __half g_xh [(size_t)NPTS * C];    // x fp16
__device__ __half g_o1 [(size_t)NPTS * CH];   // out1, plain fp16
__device__ __half g_Wvh[C * CH], g_Wvl[C * CH];
__device__ __half g_Woh[CH * C], g_Wol[CH * C];
__device__ float g_P   [(size_t)NPTS * KK];   // x @ Wq^T
__device__ float g_q   [NPTS];                // raw q (pre-BN)
__device__ float g_y   [(size_t)NPTS * C];    // out1 @ Wout (pre-BN)
__device__ float g_part[2048 * 512];          // GEMM-epilogue column-stat partials
__device__ float g_qpart[2 * NSB];            // q stat partials
__device__ float g_vab [2 * CH];              // v BN affine (a, b)
__device__ float g_qab [2];                   // q BN affine
__device__ float g_yab [2 * C];               // y BN affine
__device__ float g_ksum[MM * KK];             // cb.sum(-1)

__device__ __forceinline__ void split2(float f, __half& hi, __half& lo) {
    hi = __float2half_rn(f);
    lo = __float2half_rn(f - __half2float(hi));
}

// ---------------- prep: weight splits + ksum, one kernel -----------------------
__global__ void __launch_bounds__(256) prep_kernel(
    const float* __restrict__ Wv, const float* __restrict__ Wout,
    const float* __restrict__ cb,
    __half2* __restrict__ Wvh, __half2* __restrict__ Wvl,
    __half2* __restrict__ Woh, __half2* __restrict__ Wol,
    float* __restrict__ ks)
{
    const int b = blockIdx.x;
    if (b < 64) {
        const bool isWv = b < 32;
        const int i = (isWv ? b : b - 32) * 256 + threadIdx.x;  // < 8192 float4
        float4 v = (isWv ? (const float4*)Wv : (const float4*)Wout)[i];
        __half h0,l0,h1,l1,h2,l2,h3,l3;
        split2(v.x,h0,l0); split2(v.y,h1,l1); split2(v.z,h2,l2); split2(v.w,h3,l3);
        __half2* oh = isWv ? Wvh : Woh;
        __half2* ol = isWv ? Wvl : Wol;
        oh[2*i]   = __halves2half2(h0,h1); oh[2*i+1] = __halves2half2(h2,h3);
        ol[2*i]   = __halves2half2(l0,l1); ol[2*i+1] = __halves2half2(l2,l3);
    } else {
        __shared__ float sh[256];
        const int row = b - 64;   // 0..53
        sh[threadIdx.x] = cb[(size_t)row * CH + threadIdx.x];
        __syncthreads();
        for (int o = 128; o; o >>= 1) {
            if (threadIdx.x < o) sh[threadIdx.x] += sh[threadIdx.x + o];
            __syncthreads();
        }
        if (threadIdx.x == 0) ks[row] = sh[0];
    }
}

// =====================================================================
// fp16 tensor-core GEMM, cp.async double-buffered, fused column stats.
// SPLIT_A=true : D = Ah*Bh + Ah*Bl + Al*Bh
// SPLIT_A=false: D = A*Bh  + A*Bl
// =====================================================================
constexpr int APITCH = 40;
constexpr int BPITCH = 136;
constexpr int HG_SMEM = (2 * 2 * 128 * APITCH + 2 * 2 * 32 * BPITCH) * 2;

__device__ __forceinline__ void cpasync16(__half* dst, const __half* src) {
    unsigned d = (unsigned)__cvta_generic_to_shared(dst);
    asm volatile("cp.async.cg.shared.global [%0], [%1], 16;\n" :: "r"(d), "l"(src));
}

template<int Kd, bool HALF_OUT, bool SPLIT_A>
__global__ void __launch_bounds__(256) hgemm16(
    const __half* __restrict__ Ahg, const __half* __restrict__ Alg,
    const __half* __restrict__ Bhg, const __half* __restrict__ Blg,
    void* __restrict__ Cout, int Ncols, float* __restrict__ part)
{
    extern __shared__ float smraw[];
    __half* As = reinterpret_cast<__half*>(smraw);
    __half* Bs = As + 2 * 2 * 128 * APITCH;

    const int tid  = threadIdx.x;
    const int warp = tid >> 5, lane = tid & 31;
    const int wm = warp >> 2;
    const int wn = warp & 3;
    const int rowBase = blockIdx.x * 128;
    const int colBase = blockIdx.y * 128;
    constexpr int KT = Kd / 32;

    float acc[4][4][4];
#pragma unroll
    for (int i = 0; i < 4; i++)
#pragma unroll
        for (int j = 0; j < 4; j++)
#pragma unroll
            for (int f = 0; f < 4; f++) acc[i][j][f] = 0.f;

    auto load_stage = [&](int s, int k0) {
        __half* Ah_s = As + (s * 2 + 0) * (128 * APITCH);
        __half* Al_s = As + (s * 2 + 1) * (128 * APITCH);
        __half* Bh_s = Bs + (s * 2 + 0) * (32 * BPITCH);
        __half* Bl_s = Bs + (s * 2 + 1) * (32 * BPITCH);
#pragma unroll
        for (int it = 0; it < 2; it++) {
            int idx = it * 256 + tid;
            int r = idx >> 2, q = idx & 3;
            size_t ga = (size_t)(rowBase + r) * Kd + k0 + q * 8;
            cpasync16(&Ah_s[r * APITCH + q * 8], &Ahg[ga]);
            if constexpr (SPLIT_A)
                cpasync16(&Al_s[r * APITCH + q * 8], &Alg[ga]);
            int rb = idx >> 4, qb = idx & 15;
            size_t gb = (size_t)(k0 + rb) * Ncols + colBase + qb * 8;
            cpasync16(&Bh_s[rb * BPITCH + qb * 8], &Bhg[gb]);
            cpasync16(&Bl_s[rb * BPITCH + qb * 8], &Blg[gb]);
        }
        asm volatile("cp.async.commit_group;\n" ::);
    };

    load_stage(0, 0);

    for (int kt = 0; kt < KT; kt++) {
        if (kt + 1 < KT) {
            load_stage((kt + 1) & 1, (kt + 1) * 32);
            asm volatile("cp.async.wait_group 1;\n" ::);
        } else {
            asm volatile("cp.async.wait_group 0;\n" ::);
        }
        __syncthreads();

        const int s = kt & 1;
        const __half* Ah_s = As + (s * 2 + 0) * (128 * APITCH);
        const __half* Al_s = As + (s * 2 + 1) * (128 * APITCH);
        const __half* Bh_s = Bs + (s * 2 + 0) * (32 * BPITCH);
        const __half* Bl_s = Bs + (s * 2 + 1) * (32 * BPITCH);

#pragma unroll
        for (int ks = 0; ks < 32; ks += 16) {
            unsigned ah[4][4], al[4][4];
#pragma unroll
            for (int mt = 0; mt < 4; mt++) {
                int row = wm * 64 + mt * 16 + (lane & 15);
                int col = ks + (lane >> 4) * 8;
                unsigned aH = (unsigned)__cvta_generic_to_shared(&Ah_s[row * APITCH + col]);
                asm volatile("ldmatrix.sync.aligned.m8n8.x4.shared.b16 {%0,%1,%2,%3}, [%4];"
                    : "=r"(ah[mt][0]),"=r"(ah[mt][1]),"=r"(ah[mt][2]),"=r"(ah[mt][3]) : "r"(aH));
                if constexpr (SPLIT_A) {
                    unsigned aL = (unsigned)__cvta_generic_to_shared(&Al_s[row * APITCH + col]);
                    asm volatile("ldmatrix.sync.aligned.m8n8.x4.shared.b16 {%0,%1,%2,%3}, [%4];"
                        : "=r"(al[mt][0]),"=r"(al[mt][1]),"=r"(al[mt][2]),"=r"(al[mt][3]) : "r"(aL));
                }
            }
            unsigned bh[4][2], bl[4][2];
#pragma unroll
            for (int pr = 0; pr < 2; pr++) {
                int krow = ks + (lane & 15);
                int col = wn * 32 + pr * 16 + (lane >> 4) * 8;
                unsigned aH = (unsigned)__cvta_generic_to_shared(&Bh_s[krow * BPITCH + col]);
                unsigned aL = (unsigned)__cvta_generic_to_shared(&Bl_s[krow * BPITCH + col]);
                asm volatile("ldmatrix.sync.aligned.m8n8.x4.trans.shared.b16 {%0,%1,%2,%3}, [%4];"
                    : "=r"(bh[pr*2][0]),"=r"(bh[pr*2][1]),"=r"(bh[pr*2+1][0]),"=r"(bh[pr*2+1][1]) : "r"(aH));
                asm volatile("ldmatrix.sync.aligned.m8n8.x4.trans.shared.b16 {%0,%1,%2,%3}, [%4];"
                    : "=r"(bl[pr*2][0]),"=r"(bl[pr*2][1]),"=r"(bl[pr*2+1][0]),"=r"(bl[pr*2+1][1]) : "r"(aL));
            }
#pragma unroll
            for (int mt = 0; mt < 4; mt++)
#pragma unroll
                for (int nt = 0; nt < 4; nt++) {
                    float* d = acc[mt][nt];
#define MMA(Af, Bf) \
    asm volatile("mma.sync.aligned.m16n8k16.row.col.f32.f16.f16.f32 " \
        "{%0,%1,%2,%3}, {%4,%5,%6,%7}, {%8,%9}, {%0,%1,%2,%3};" \
        : "+f"(d[0]),"+f"(d[1]),"+f"(d[2]),"+f"(d[3]) \
        : "r"(Af[0]),"r"(Af[1]),"r"(Af[2]),"r"(Af[3]), "r"(Bf[0]),"r"(Bf[1]))
                    MMA(ah[mt], bh[nt]);
                    MMA(ah[mt], bl[nt]);
                    if constexpr (SPLIT_A) { MMA(al[mt], bh[nt]); }
#undef MMA
                }
        }
        __syncthreads();
    }

    // ---- output stores ----
    const int g = lane >> 2, tg = lane & 3;
#pragma unroll
    for (int mt = 0; mt < 4; mt++)
#pragma unroll
        for (int nt = 0; nt < 4; nt++) {
            size_t row = (size_t)rowBase + wm * 64 + mt * 16 + g;
            int col = colBase + wn * 32 + nt * 8 + tg * 2;
            float* d = acc[mt][nt];
            if constexpr (HALF_OUT) {
                __half* Cm = (__half*)Cout;
                *reinterpret_cast<__half2*>(&Cm[row * Ncols + col]) =
                    __floats2half2_rn(d[0], d[1]);
                *reinterpret_cast<__half2*>(&Cm[(row + 8) * Ncols + col]) =
                    __floats2half2_rn(d[2], d[3]);
            } else {
                float* Cm = (float*)Cout;
                *reinterpret_cast<float2*>(&Cm[row * Ncols + col]) =
                    make_float2(d[0], d[1]);
                *reinterpret_cast<float2*>(&Cm[(row + 8) * Ncols + col]) =
                    make_float2(d[2], d[3]);
            }
        }

    // ---- fused column stats ----
#pragma unroll
    for (int nt = 0; nt < 4; nt++) {
        float a0 = 0.f, a1 = 0.f, b0 = 0.f, b1 = 0.f;
#pragma unroll
        for (int mt = 0; mt < 4; mt++) {
            float* d = acc[mt][nt];
            a0 += d[0] + d[2];
            a1 += d[1] + d[3];
            b0 = fmaf(d[0], d[0], fmaf(d[2], d[2], b0));
            b1 = fmaf(d[1], d[1], fmaf(d[3], d[3], b1));
        }
#pragma unroll
        for (int o = 4; o <= 16; o <<= 1) {
            a0 += __shfl_xor_sync(0xFFFFFFFFu, a0, o);
            a1 += __shfl_xor_sync(0xFFFFFFFFu, a1, o);
            b0 += __shfl_xor_sync(0xFFFFFFFFu, b0, o);
            b1 += __shfl_xor_sync(0xFFFFFFFFu, b1, o);
        }
        if ((lane >> 2) == 0) {
            float* pb = part +
                ((size_t)(blockIdx.y * gridDim.x + blockIdx.x) * 2 + wm) * 256;
            int c0 = wn * 32 + nt * 8 + lane * 2;
            pb[c0]           = a0;
            pb[c0 + 1]       = a1;
            pb[128 + c0]     = b0;
            pb[128 + c0 + 1] = b1;
        }
    }
}

// ---------------- generic affine reduce over GEMM partials --------------------
__global__ void reduce_affine(const float* __restrict__ part,
    const float* __restrict__ gg, const float* __restrict__ bb,
    float* __restrict__ ab, float invN, int nbx, int CC)
{
    const int c = blockIdx.x;
    const int y = c >> 7, cc = c & 127;
    float s = 0.f, s2 = 0.f;
    for (int b = threadIdx.x; b < nbx * 2; b += 256) {
        const float* p = part + ((size_t)(y * nbx + (b >> 1)) * 2 + (b & 1)) * 256;
        s += p[cc]; s2 += p[128 + cc];
    }
    __shared__ float shm[512];
    shm[threadIdx.x] = s; shm[256 + threadIdx.x] = s2;
    __syncthreads();
    for (int o = 128; o; o >>= 1) {
        if (threadIdx.x < o) {
            shm[threadIdx.x] += shm[threadIdx.x + o];
            shm[256 + threadIdx.x] += shm[256 + threadIdx.x + o];
        }
        __syncthreads();
    }
    if (threadIdx.x == 0) {
        float mu  = shm[0] * invN;
        float var = fmaf(-mu, mu, shm[256] * invN);
        float a = gg[c] * rsqrtf(var + EPSV);
        ab[c] = a;
        ab[CC + c] = fmaf(-mu, a, bb[c]);
    }
}

// ---------------- P = x @ Wq^T + fused fp16 cast of x --------------------------
__global__ void __launch_bounds__(256) p_gemm(
    const float* __restrict__ x, const float* __restrict__ Wq,
    float* __restrict__ P, __half2* __restrict__ xh)
{
    __shared__ float wqs[KK * C];
    __shared__ float red[8][KK * 32];
    for (int i = threadIdx.x; i < KK * C; i += 256) wqs[i] = Wq[i];
    __syncthreads();
    const int warp = threadIdx.x >> 5, lane = threadIdx.x & 31;
    const int row = blockIdx.x * 8 + warp;
    float4 xv = reinterpret_cast<const float4*>(x + (size_t)row * C)[lane];

    {
        const size_t base = (size_t)row * 64 + lane * 2;
        xh[base]     = __floats2half2_rn(xv.x, xv.y);
        xh[base + 1] = __floats2half2_rn(xv.z, xv.w);
    }

    float part[KK];
#pragma unroll
    for (int k = 0; k < KK; k++) {
        float4 w = reinterpret_cast<const float4*>(wqs + k * C)[lane];
        part[k] = xv.x * w.x + xv.y * w.y + xv.z * w.z + xv.w * w.w;
    }
#pragma unroll
    for (int k = 0; k < KK; k++) red[warp][lane * KK + k] = part[k];
    __syncwarp();
    if (lane < KK) {
        float s = 0.f;
#pragma unroll
        for (int j = 0; j < 32; j++) s += red[warp][j * KK + lane];
        P[(size_t)row * KK + lane] = s;
    }
}

// ---------------- vr = relu(bn(v)) as fp16 -------------------------------------
__global__ void __launch_bounds__(256) vrelu_kernel(
    const __half2* __restrict__ vh, const float* __restrict__ vab,
    __half2* __restrict__ vr, int n2)
{
    int i = blockIdx.x * 256 + threadIdx.x;
    if (i >= n2) return;
    int c2 = i & 127;
    float2 a = reinterpret_cast<const float2*>(vab)[c2];
    float2 b = reinterpret_cast<const float2*>(vab + CH)[c2];
    float2 v = __half22float2(vh[i]);
    vr[i] = __floats2half2_rn(fmaxf(fmaf(v.x, a.x, b.x), 0.f),
                              fmaxf(fmaf(v.y, a.y, b.y), 0.f));
}

// ---------------- q[n] = sum_k P[nbr[n,k], k] + stats -------------------------
__global__ void q_gather(const int* __restrict__ nbr, const float* __restrict__ P,
                         float* __restrict__ q, float* __restrict__ qpart)
{
    const int n = blockIdx.x * 256 + threadIdx.x;
    float s = 0.f;
#pragma unroll
    for (int k = 0; k < KK; k++) {
        int idx = nbr[(size_t)n * KK + k];
        s += P[(size_t)idx * KK + k];
    }
    q[n] = s;
    __shared__ float sh[512];
    sh[threadIdx.x] = s;
    sh[256 + threadIdx.x] = s * s;
    __syncthreads();
    for (int o = 128; o; o >>= 1) {
        if (threadIdx.x < o) {
            sh[threadIdx.x] += sh[threadIdx.x + o];
            sh[256 + threadIdx.x] += sh[256 + threadIdx.x + o];
        }
        __syncthreads();
    }
    if (threadIdx.x == 0) {
        qpart[blockIdx.x] = sh[0];
        qpart[NSB + blockIdx.x] = sh[256];
    }
}

__global__ void q_finalize(const float* __restrict__ qpart,
    const float* __restrict__ gq, const float* __restrict__ bq,
    float* __restrict__ qab, float invN)
{
    __shared__ float sh[2 * NSB];
    sh[threadIdx.x] = qpart[threadIdx.x];
    sh[NSB + threadIdx.x] = qpart[NSB + threadIdx.x];
    __syncthreads();
    for (int o = NSB / 2; o; o >>= 1) {
        if (threadIdx.x < o) {
            sh[threadIdx.x] += sh[threadIdx.x + o];
            sh[NSB + threadIdx.x] += sh[NSB + threadIdx.x + o];
        }
        __syncthreads();
    }
    if (threadIdx.x == 0) {
        float mu  = sh[0] * invN;
        float var = fmaf(-mu, mu, sh[NSB] * invN);
        float a = gq[0] * rsqrtf(var + EPSV);
        qab[0] = a;
        qab[1] = fmaf(-mu, a, bq[0]);
    }
}

// ---------------- routed gather: inline choice (no s_q), fp16 out --------------
// smem = (2*27*256 + 2*16 + 27*16 + 2*27)*4 = 57368 B  -> 4 blocks/SM (<= 58368)
constexpr int RG_ROWS = 16;
constexpr int RG_SMEM = (2 * KK * CH + 2 * RG_ROWS + KK * RG_ROWS + 2 * KK) * 4;

__global__ void __launch_bounds__(256) routed_gather(
    const __half2* __restrict__ vr, const int* __restrict__ nbr,
    const float* __restrict__ q, const float* __restrict__ qab,
    const float* __restrict__ ks, const float* __restrict__ cb,
    __half2* __restrict__ o1)
{
    extern __shared__ float sm[];
    float* s_cb = sm;                           // 2*27*256
    float* s_ch = s_cb + 2 * KK * CH;           // 2*16
    float* s_ks = s_ch + 2 * RG_ROWS;           // 2*27
    int*   s_idx = (int*)(s_ks + 2 * KK);       // 27*16
    const int tid = threadIdx.x;
    const int grp = tid >> 6;        // 0..3 -> rows j*4+grp
    const int c4  = tid & 63;        // channel quad
    const int n0 = blockIdx.x * RG_ROWS;

    for (int i = tid; i < 2 * KK * CH; i += 256) s_cb[i] = cb[i];
    if (tid < 2 * KK) s_ks[tid] = ks[tid];
    for (int i = tid; i < KK * RG_ROWS; i += 256) s_idx[i] = nbr[(size_t)n0 * KK + i];
    __syncthreads();
    // inline per-row routing softmax: threads 0..15 gather q directly (27 loads,
    // fully overlapped; once per block so latency is noise). No s_q staging.
    if (tid < RG_ROWS) {
        const float a = qab[0], b = qab[1];
        float l0 = 0.f, l1 = 0.f;
#pragma unroll
        for (int k = 0; k < KK; k++) {
            float qq = fmaxf(fmaf(q[s_idx[tid * KK + k]], a, b), 0.f);
            l0 = fmaf(qq, s_ks[k], l0);
            l1 = fmaf(qq, s_ks[KK + k], l1);
        }
        float m = fmaxf(l0, l1);
        float e0 = expf(l0 - m), e1 = expf(l1 - m);
        float inv = 1.f / (e0 + e1);
        s_ch[2 * tid]     = e0 * inv;
        s_ch[2 * tid + 1] = e1 * inv;
    }
    __syncthreads();

    float4 acc0[4], acc1[4];
#pragma unroll
    for (int j = 0; j < 4; j++) {
        acc0[j] = make_float4(0.f, 0.f, 0.f, 0.f);
        acc1[j] = make_float4(0.f, 0.f, 0.f, 0.f);
    }

    for (int k = 0; k < KK; k++) {
        const float4 w0 = reinterpret_cast<const float4*>(s_cb + k * CH)[c4];
        const float4 w1 = reinterpret_cast<const float4*>(s_cb + (KK + k) * CH)[c4];
#pragma unroll
        for (int j = 0; j < 4; j++) {
            const int r = j * 4 + grp;
            const int idx = s_idx[r * KK + k];
            const int2 raw = __ldcg(reinterpret_cast<const int2*>(
                vr + (size_t)idx * 128 + c4 * 2));
            const float2 va = __half22float2(*reinterpret_cast<const __half2*>(&raw.x));
            const float2 vb = __half22float2(*reinterpret_cast<const __half2*>(&raw.y));
            acc0[j].x = fmaf(va.x, w0.x, acc0[j].x);
            acc0[j].y = fmaf(va.y, w0.y, acc0[j].y);
            acc0[j].z = fmaf(vb.x, w0.z, acc0[j].z);
            acc0[j].w = fmaf(vb.y, w0.w, acc0[j].w);
            acc1[j].x = fmaf(va.x, w1.x, acc1[j].x);
            acc1[j].y = fmaf(va.y, w1.y, acc1[j].y);
            acc1[j].z = fmaf(vb.x, w1.z, acc1[j].z);
            acc1[j].w = fmaf(vb.y, w1.w, acc1[j].w);
        }
    }
#pragma unroll
    for (int j = 0; j < 4; j++) {
        const int r = j * 4 + grp;
        const float c0 = s_ch[2 * r], c1 = s_ch[2 * r + 1];
        float o0 = fmaf(c0, acc0[j].x, c1 * acc1[j].x);
        float o1v = fmaf(c0, acc0[j].y, c1 * acc1[j].y);
        float o2 = fmaf(c0, acc0[j].z, c1 * acc1[j].z);
        float o3 = fmaf(c0, acc0[j].w, c1 * acc1[j].w);
        const size_t base = (size_t)(n0 + r) * 128 + c4 * 2;
        o1[base]     = __floats2half2_rn(o0, o1v);
        o1[base + 1] = __floats2half2_rn(o2, o3);
    }
}

// ---------------- final: relu(bn(y)) + x, float4 vectorized ---------------------
__global__ void __launch_bounds__(256) final_kernel(
    const float4* __restrict__ y, const float4* __restrict__ x,
    const float* __restrict__ yab, float4* __restrict__ out)
{
    const int i = blockIdx.x * 256 + threadIdx.x;
    const int c4 = i & 31;
    const float4 a = reinterpret_cast<const float4*>(yab)[c4];
    const float4 b = reinterpret_cast<const float4*>(yab + C)[c4];
    const float4 yv = y[i];
    const float4 xv = x[i];
    float4 o;
    o.x = fmaxf(fmaf(yv.x, a.x, b.x), 0.f) + xv.x;
    o.y = fmaxf(fmaf(yv.y, a.y, b.y), 0.f) + xv.y;
    o.z = fmaxf(fmaf(yv.z, a.z, b.z), 0.f) + xv.z;
    o.w = fmaxf(fmaf(yv.w, a.w, b.w), 0.f) + xv.w;
    out[i] = o;
}

// ---------------- launch -------------------------------------------------------
extern "C" void kernel_launch(void* const* d_in, const int* in_sizes, int n_in,
                              void* d_out, int out_size)
{
    const float* x    = (const float*)d_in[0];
    const int*   nbr  = (const int*)  d_in[1];
    const float* Wv   = (const float*)d_in[2];
    const float* gv   = (const float*)d_in[3];
    const float* bv   = (const float*)d_in[4];
    const float* Wq   = (const float*)d_in[5];
    const float* gq   = (const float*)d_in[6];
    const float* bq   = (const float*)d_in[7];
    const float* cb   = (const float*)d_in[8];
    const float* Wout = (const float*)d_in[9];
    const float* go   = (const float*)d_in[10];
    const float* bo   = (const float*)d_in[11];
    float* out = (float*)d_out;
    const int N = in_sizes[0] / C;

    __half *pvh, *pvr, *pxh, *po1, *pWvh, *pWvl, *pWoh, *pWol;
    float *pP, *pq, *py, *ppart, *pqpart, *pvab, *pqab, *pyab, *pksum;
    cudaGetSymbolAddress((void**)&pvh,    g_vh);
    cudaGetSymbolAddress((void**)&pvr,    g_vr);
    cudaGetSymbolAddress((void**)&pxh,    g_xh);
    cudaGetSymbolAddress((void**)&po1,    g_o1);
    cudaGetSymbolAddress((void**)&pWvh,   g_Wvh);
    cudaGetSymbolAddress((void**)&pWvl,   g_Wvl);
    cudaGetSymbolAddress((void**)&pWoh,   g_Woh);
    cudaGetSymbolAddress((void**)&pWol,   g_Wol);
    cudaGetSymbolAddress((void**)&pP,     g_P);
    cudaGetSymbolAddress((void**)&pq,     g_q);
    cudaGetSymbolAddress((void**)&py,     g_y);
    cudaGetSymbolAddress((void**)&ppart,  g_part);
    cudaGetSymbolAddress((void**)&pqpart, g_qpart);
    cudaGetSymbolAddress((void**)&pvab,   g_vab);
    cudaGetSymbolAddress((void**)&pqab,   g_qab);
    cudaGetSymbolAddress((void**)&pyab,   g_yab);
    cudaGetSymbolAddress((void**)&pksum,  g_ksum);

    cudaFuncSetAttribute(routed_gather,
                         cudaFuncAttributeMaxDynamicSharedMemorySize, RG_SMEM);
    cudaFuncSetAttribute((hgemm16<128, true, false>),
                         cudaFuncAttributeMaxDynamicSharedMemorySize, HG_SMEM);
    cudaFuncSetAttribute((hgemm16<256, false, false>),
                         cudaFuncAttributeMaxDynamicSharedMemorySize, HG_SMEM);

    const float invN = 1.f / (float)N;

    // weight splits + ksum (one kernel)
    prep_kernel<<<64 + MM * KK, 256>>>(Wv, Wout, cb,
        (__half2*)pWvh, (__half2*)pWvl, (__half2*)pWoh, (__half2*)pWol, pksum);
    // P = x @ Wq^T, also emits x as fp16
    p_gemm<<<N / 8, 256>>>(x, Wq, pP, (__half2*)pxh);
    // v = x @ Wv  (plain-A fp16 GEMM, split-B, fp16 out, fused column stats)
    hgemm16<128, true, false><<<dim3(N / 128, CH / 128), 256, HG_SMEM>>>(
        pxh, nullptr, pWvh, pWvl, pvh, CH, ppart);
    reduce_affine<<<CH, 256>>>(ppart, gv, bv, pvab, invN, N / 128, CH);
    // vr = relu(bn(v)) fp16
    {
        const int n2 = N * CH / 2;
        vrelu_kernel<<<n2 / 256, 256>>>(
            (const __half2*)pvh, pvab, (__half2*)pvr, n2);
    }
    // q pipeline
    q_gather<<<N / 256, 256>>>(nbr, pP, pq, pqpart);
    q_finalize<<<1, NSB>>>(pqpart, gq, bq, pqab, invN);
    // routed channelwise gather conv with inline routing softmax -> fp16 out1
    routed_gather<<<N / RG_ROWS, 256, RG_SMEM>>>(
        (const __half2*)pvr, nbr, pq, pqab, pksum, cb, (__half2*)po1);
    // y = out1 @ Wout (plain-A fp16 GEMM, split B, fp32 out, fused stats)
    hgemm16<256, false, false><<<dim3(N / 128, 1), 256, HG_SMEM>>>(
        po1, nullptr, pWoh, pWol, py, C, ppart);
    reduce_affine<<<C, 256>>>(ppart, go, bo, pyab, invN, N / 128, C);
    // out = relu(bn(y)) + x (float4 vectorized)
    final_kernel<<<(size_t)N * C / 4 / 256, 256>>>(
        (const float4*)py, (const float4*)x, pyab, (float4*)out);
}

// round 14
// speedup vs baseline: 1.1128x; 1.1128x over previous
#include <cuda_runtime.h>
#include <cuda_fp16.h>
#include <math.h>

#define EPSV 1e-5f

constexpr int C   = 128;
constexpr int CH  = 256;   // C*H
constexpr int KK  = 27;
constexpr int MM  = 2;
constexpr int NPTS = 131072;
constexpr int NSB = 512;   // q stat partial blocks

// ---------------- device scratch (static; no allocations allowed) --------------
__device__ __half g_vh [(size_t)NPTS * CH];   // x @ Wv (pre-BN), fp16
__device__ __half g_vr [(size_t)NPTS * CH];   // relu(bn(v)), fp16
__device__ __half g_xh [(size_t)NPTS * C];    // x fp16
__device__ __half g_o1 [(size_t)NPTS * CH];   // out1, plain fp16
__device__ __half g_Wvh[C * CH], g_Wvl[C * CH];
__device__ __half g_Woh[CH * C], g_Wol[CH * C];
__device__ float g_P   [(size_t)NPTS * KK];   // x @ Wq^T
__device__ float g_q   [NPTS];                // raw q (pre-BN)
__device__ float g_y   [(size_t)NPTS * C];    // out1 @ Wout (pre-BN)
__device__ float g_part[2048 * 512];          // GEMM-epilogue column-stat partials
__device__ float g_qpart[2 * NSB];            // q stat partials
__device__ float g_vab [2 * CH];              // v BN affine (a, b)
__device__ float g_qab [2];                   // q BN affine
__device__ float g_yab [2 * C];               // y BN affine
__device__ float g_ksum[MM * KK];             // cb.sum(-1)
__device__ float g_choice[(size_t)NPTS * MM];

__device__ __forceinline__ void split2(float f, __half& hi, __half& lo) {
    hi = __float2half_rn(f);
    lo = __float2half_rn(f - __half2float(hi));
}

// ---------------- prep: weight splits + ksum, one kernel -----------------------
__global__ void __launch_bounds__(256) prep_kernel(
    const float* __restrict__ Wv, const float* __restrict__ Wout,
    const float* __restrict__ cb,
    __half2* __restrict__ Wvh, __half2* __restrict__ Wvl,
    __half2* __restrict__ Woh, __half2* __restrict__ Wol,
    float* __restrict__ ks)
{
    const int b = blockIdx.x;
    if (b < 64) {
        const bool isWv = b < 32;
        const int i = (isWv ? b : b - 32) * 256 + threadIdx.x;  // < 8192 float4
        float4 v = (isWv ? (const float4*)Wv : (const float4*)Wout)[i];
        __half h0,l0,h1,l1,h2,l2,h3,l3;
        split2(v.x,h0,l0); split2(v.y,h1,l1); split2(v.z,h2,l2); split2(v.w,h3,l3);
        __half2* oh = isWv ? Wvh : Woh;
        __half2* ol = isWv ? Wvl : Wol;
        oh[2*i]   = __halves2half2(h0,h1); oh[2*i+1] = __halves2half2(h2,h3);
        ol[2*i]   = __halves2half2(l0,l1); ol[2*i+1] = __halves2half2(l2,l3);
    } else {
        __shared__ float sh[256];
        const int row = b - 64;   // 0..53
        sh[threadIdx.x] = cb[(size_t)row * CH + threadIdx.x];
        __syncthreads();
        for (int o = 128; o; o >>= 1) {
            if (threadIdx.x < o) sh[threadIdx.x] += sh[threadIdx.x + o];
            __syncthreads();
        }
        if (threadIdx.x == 0) ks[row] = sh[0];
    }
}

// =====================================================================
// fp16 tensor-core GEMM, cp.async double-buffered, fused column stats.
// SPLIT_A=true : D = Ah*Bh + Ah*Bl + Al*Bh
// SPLIT_A=false: D = A*Bh  + A*Bl
// =====================================================================
constexpr int APITCH = 40;
constexpr int BPITCH = 136;
constexpr int HG_SMEM = (2 * 2 * 128 * APITCH + 2 * 2 * 32 * BPITCH) * 2;

__device__ __forceinline__ void cpasync16(__half* dst, const __half* src) {
    unsigned d = (unsigned)__cvta_generic_to_shared(dst);
    asm volatile("cp.async.cg.shared.global [%0], [%1], 16;\n" :: "r"(d), "l"(src));
}

template<int Kd, bool HALF_OUT, bool SPLIT_A>
__global__ void __launch_bounds__(256) hgemm16(
    const __half* __restrict__ Ahg, const __half* __restrict__ Alg,
    const __half* __restrict__ Bhg, const __half* __restrict__ Blg,
    void* __restrict__ Cout, int Ncols, float* __restrict__ part)
{
    extern __shared__ float smraw[];
    __half* As = reinterpret_cast<__half*>(smraw);
    __half* Bs = As + 2 * 2 * 128 * APITCH;

    const int tid  = threadIdx.x;
    const int warp = tid >> 5, lane = tid & 31;
    const int wm = warp >> 2;
    const int wn = warp & 3;
    const int rowBase = blockIdx.x * 128;
    const int colBase = blockIdx.y * 128;
    constexpr int KT = Kd / 32;

    float acc[4][4][4];
#pragma unroll
    for (int i = 0; i < 4; i++)
#pragma unroll
        for (int j = 0; j < 4; j++)
#pragma unroll
            for (int f = 0; f < 4; f++) acc[i][j][f] = 0.f;

    auto load_stage = [&](int s, int k0) {
        __half* Ah_s = As + (s * 2 + 0) * (128 * APITCH);
        __half* Al_s = As + (s * 2 + 1) * (128 * APITCH);
        __half* Bh_s = Bs + (s * 2 + 0) * (32 * BPITCH);
        __half* Bl_s = Bs + (s * 2 + 1) * (32 * BPITCH);
#pragma unroll
        for (int it = 0; it < 2; it++) {
            int idx = it * 256 + tid;
            int r = idx >> 2, q = idx & 3;
            size_t ga = (size_t)(rowBase + r) * Kd + k0 + q * 8;
            cpasync16(&Ah_s[r * APITCH + q * 8], &Ahg[ga]);
            if constexpr (SPLIT_A)
                cpasync16(&Al_s[r * APITCH + q * 8], &Alg[ga]);
            int rb = idx >> 4, qb = idx & 15;
            size_t gb = (size_t)(k0 + rb) * Ncols + colBase + qb * 8;
            cpasync16(&Bh_s[rb * BPITCH + qb * 8], &Bhg[gb]);
            cpasync16(&Bl_s[rb * BPITCH + qb * 8], &Blg[gb]);
        }
        asm volatile("cp.async.commit_group;\n" ::);
    };

    load_stage(0, 0);

    for (int kt = 0; kt < KT; kt++) {
        if (kt + 1 < KT) {
            load_stage((kt + 1) & 1, (kt + 1) * 32);
            asm volatile("cp.async.wait_group 1;\n" ::);
        } else {
            asm volatile("cp.async.wait_group 0;\n" ::);
        }
        __syncthreads();

        const int s = kt & 1;
        const __half* Ah_s = As + (s * 2 + 0) * (128 * APITCH);
        const __half* Al_s = As + (s * 2 + 1) * (128 * APITCH);
        const __half* Bh_s = Bs + (s * 2 + 0) * (32 * BPITCH);
        const __half* Bl_s = Bs + (s * 2 + 1) * (32 * BPITCH);

#pragma unroll
        for (int ks = 0; ks < 32; ks += 16) {
            unsigned ah[4][4], al[4][4];
#pragma unroll
            for (int mt = 0; mt < 4; mt++) {
                int row = wm * 64 + mt * 16 + (lane & 15);
                int col = ks + (lane >> 4) * 8;
                unsigned aH = (unsigned)__cvta_generic_to_shared(&Ah_s[row * APITCH + col]);
                asm volatile("ldmatrix.sync.aligned.m8n8.x4.shared.b16 {%0,%1,%2,%3}, [%4];"
                    : "=r"(ah[mt][0]),"=r"(ah[mt][1]),"=r"(ah[mt][2]),"=r"(ah[mt][3]) : "r"(aH));
                if constexpr (SPLIT_A) {
                    unsigned aL = (unsigned)__cvta_generic_to_shared(&Al_s[row * APITCH + col]);
                    asm volatile("ldmatrix.sync.aligned.m8n8.x4.shared.b16 {%0,%1,%2,%3}, [%4];"
                        : "=r"(al[mt][0]),"=r"(al[mt][1]),"=r"(al[mt][2]),"=r"(al[mt][3]) : "r"(aL));
                }
            }
            unsigned bh[4][2], bl[4][2];
#pragma unroll
            for (int pr = 0; pr < 2; pr++) {
                int krow = ks + (lane & 15);
                int col = wn * 32 + pr * 16 + (lane >> 4) * 8;
                unsigned aH = (unsigned)__cvta_generic_to_shared(&Bh_s[krow * BPITCH + col]);
                unsigned aL = (unsigned)__cvta_generic_to_shared(&Bl_s[krow * BPITCH + col]);
                asm volatile("ldmatrix.sync.aligned.m8n8.x4.trans.shared.b16 {%0,%1,%2,%3}, [%4];"
                    : "=r"(bh[pr*2][0]),"=r"(bh[pr*2][1]),"=r"(bh[pr*2+1][0]),"=r"(bh[pr*2+1][1]) : "r"(aH));
                asm volatile("ldmatrix.sync.aligned.m8n8.x4.trans.shared.b16 {%0,%1,%2,%3}, [%4];"
                    : "=r"(bl[pr*2][0]),"=r"(bl[pr*2][1]),"=r"(bl[pr*2+1][0]),"=r"(bl[pr*2+1][1]) : "r"(aL));
            }
#pragma unroll
            for (int mt = 0; mt < 4; mt++)
#pragma unroll
                for (int nt = 0; nt < 4; nt++) {
                    float* d = acc[mt][nt];
#define MMA(Af, Bf) \
    asm volatile("mma.sync.aligned.m16n8k16.row.col.f32.f16.f16.f32 " \
        "{%0,%1,%2,%3}, {%4,%5,%6,%7}, {%8,%9}, {%0,%1,%2,%3};" \
        : "+f"(d[0]),"+f"(d[1]),"+f"(d[2]),"+f"(d[3]) \
        : "r"(Af[0]),"r"(Af[1]),"r"(Af[2]),"r"(Af[3]), "r"(Bf[0]),"r"(Bf[1]))
                    MMA(ah[mt], bh[nt]);
                    MMA(ah[mt], bl[nt]);
                    if constexpr (SPLIT_A) { MMA(al[mt], bh[nt]); }
#undef MMA
                }
        }
        __syncthreads();
    }

    // ---- output stores ----
    const int g = lane >> 2, tg = lane & 3;
#pragma unroll
    for (int mt = 0; mt < 4; mt++)
#pragma unroll
        for (int nt = 0; nt < 4; nt++) {
            size_t row = (size_t)rowBase + wm * 64 + mt * 16 + g;
            int col = colBase + wn * 32 + nt * 8 + tg * 2;
            float* d = acc[mt][nt];
            if constexpr (HALF_OUT) {
                __half* Cm = (__half*)Cout;
                *reinterpret_cast<__half2*>(&Cm[row * Ncols + col]) =
                    __floats2half2_rn(d[0], d[1]);
                *reinterpret_cast<__half2*>(&Cm[(row + 8) * Ncols + col]) =
                    __floats2half2_rn(d[2], d[3]);
            } else {
                float* Cm = (float*)Cout;
                *reinterpret_cast<float2*>(&Cm[row * Ncols + col]) =
                    make_float2(d[0], d[1]);
                *reinterpret_cast<float2*>(&Cm[(row + 8) * Ncols + col]) =
                    make_float2(d[2], d[3]);
            }
        }

    // ---- fused column stats ----
#pragma unroll
    for (int nt = 0; nt < 4; nt++) {
        float a0 = 0.f, a1 = 0.f, b0 = 0.f, b1 = 0.f;
#pragma unroll
        for (int mt = 0; mt < 4; mt++) {
            float* d = acc[mt][nt];
            a0 += d[0] + d[2];
            a1 += d[1] + d[3];
            b0 = fmaf(d[0], d[0], fmaf(d[2], d[2], b0));
            b1 = fmaf(d[1], d[1], fmaf(d[3], d[3], b1));
        }
#pragma unroll
        for (int o = 4; o <= 16; o <<= 1) {
            a0 += __shfl_xor_sync(0xFFFFFFFFu, a0, o);
            a1 += __shfl_xor_sync(0xFFFFFFFFu, a1, o);
            b0 += __shfl_xor_sync(0xFFFFFFFFu, b0, o);
            b1 += __shfl_xor_sync(0xFFFFFFFFu, b1, o);
        }
        if ((lane >> 2) == 0) {
            float* pb = part +
                ((size_t)(blockIdx.y * gridDim.x + blockIdx.x) * 2 + wm) * 256;
            int c0 = wn * 32 + nt * 8 + lane * 2;
            pb[c0]           = a0;
            pb[c0 + 1]       = a1;
            pb[128 + c0]     = b0;
            pb[128 + c0 + 1] = b1;
        }
    }
}

// ---------------- generic affine reduce over GEMM partials --------------------
__global__ void reduce_affine(const float* __restrict__ part,
    const float* __restrict__ gg, const float* __restrict__ bb,
    float* __restrict__ ab, float invN, int nbx, int CC)
{
    const int c = blockIdx.x;
    const int y = c >> 7, cc = c & 127;
    float s = 0.f, s2 = 0.f;
    for (int b = threadIdx.x; b < nbx * 2; b += 256) {
        const float* p = part + ((size_t)(y * nbx + (b >> 1)) * 2 + (b & 1)) * 256;
        s += p[cc]; s2 += p[128 + cc];
    }
    __shared__ float shm[512];
    shm[threadIdx.x] = s; shm[256 + threadIdx.x] = s2;
    __syncthreads();
    for (int o = 128; o; o >>= 1) {
        if (threadIdx.x < o) {
            shm[threadIdx.x] += shm[threadIdx.x + o];
            shm[256 + threadIdx.x] += shm[256 + threadIdx.x + o];
        }
        __syncthreads();
    }
    if (threadIdx.x == 0) {
        float mu  = shm[0] * invN;
        float var = fmaf(-mu, mu, shm[256] * invN);
        float a = gg[c] * rsqrtf(var + EPSV);
        ab[c] = a;
        ab[CC + c] = fmaf(-mu, a, bb[c]);
    }
}

// ---------------- P = x @ Wq^T + fused fp16 cast of x --------------------------
__global__ void __launch_bounds__(256) p_gemm(
    const float* __restrict__ x, const float* __restrict__ Wq,
    float* __restrict__ P, __half2* __restrict__ xh)
{
    __shared__ float wqs[KK * C];
    __shared__ float red[8][KK * 32];
    for (int i = threadIdx.x; i < KK * C; i += 256) wqs[i] = Wq[i];
    __syncthreads();
    const int warp = threadIdx.x >> 5, lane = threadIdx.x & 31;
    const int row = blockIdx.x * 8 + warp;
    float4 xv = reinterpret_cast<const float4*>(x + (size_t)row * C)[lane];

    {
        const size_t base = (size_t)row * 64 + lane * 2;
        xh[base]     = __floats2half2_rn(xv.x, xv.y);
        xh[base + 1] = __floats2half2_rn(xv.z, xv.w);
    }

    float part[KK];
#pragma unroll
    for (int k = 0; k < KK; k++) {
        float4 w = reinterpret_cast<const float4*>(wqs + k * C)[lane];
        part[k] = xv.x * w.x + xv.y * w.y + xv.z * w.z + xv.w * w.w;
    }
#pragma unroll
    for (int k = 0; k < KK; k++) red[warp][lane * KK + k] = part[k];
    __syncwarp();
    if (lane < KK) {
        float s = 0.f;
#pragma unroll
        for (int j = 0; j < 32; j++) s += red[warp][j * KK + lane];
        P[(size_t)row * KK + lane] = s;
    }
}

// ---------------- vr = relu(bn(v)) as fp16 -------------------------------------
__global__ void __launch_bounds__(256) vrelu_kernel(
    const __half2* __restrict__ vh, const float* __restrict__ vab,
    __half2* __restrict__ vr, int n2)
{
    int i = blockIdx.x * 256 + threadIdx.x;
    if (i >= n2) return;
    int c2 = i & 127;
    float2 a = reinterpret_cast<const float2*>(vab)[c2];
    float2 b = reinterpret_cast<const float2*>(vab + CH)[c2];
    float2 v = __half22float2(vh[i]);
    vr[i] = __floats2half2_rn(fmaxf(fmaf(v.x, a.x, b.x), 0.f),
                              fmaxf(fmaf(v.y, a.y, b.y), 0.f));
}

// ---------------- q[n] = sum_k P[nbr[n,k], k] + stats -------------------------
__global__ void q_gather(const int* __restrict__ nbr, const float* __restrict__ P,
                         float* __restrict__ q, float* __restrict__ qpart)
{
    const int n = blockIdx.x * 256 + threadIdx.x;
    float s = 0.f;
#pragma unroll
    for (int k = 0; k < KK; k++) {
        int idx = nbr[(size_t)n * KK + k];
        s += P[(size_t)idx * KK + k];
    }
    q[n] = s;
    __shared__ float sh[512];
    sh[threadIdx.x] = s;
    sh[256 + threadIdx.x] = s * s;
    __syncthreads();
    for (int o = 128; o; o >>= 1) {
        if (threadIdx.x < o) {
            sh[threadIdx.x] += sh[threadIdx.x + o];
            sh[256 + threadIdx.x] += sh[256 + threadIdx.x + o];
        }
        __syncthreads();
    }
    if (threadIdx.x == 0) {
        qpart[blockIdx.x] = sh[0];
        qpart[NSB + blockIdx.x] = sh[256];
    }
}

__global__ void q_finalize(const float* __restrict__ qpart,
    const float* __restrict__ gq, const float* __restrict__ bq,
    float* __restrict__ qab, float invN)
{
    __shared__ float sh[2 * NSB];
    sh[threadIdx.x] = qpart[threadIdx.x];
    sh[NSB + threadIdx.x] = qpart[NSB + threadIdx.x];
    __syncthreads();
    for (int o = NSB / 2; o; o >>= 1) {
        if (threadIdx.x < o) {
            sh[threadIdx.x] += sh[threadIdx.x + o];
            sh[NSB + threadIdx.x] += sh[NSB + threadIdx.x + o];
        }
        __syncthreads();
    }
    if (threadIdx.x == 0) {
        float mu  = sh[0] * invN;
        float var = fmaf(-mu, mu, sh[NSB] * invN);
        float a = gq[0] * rsqrtf(var + EPSV);
        qab[0] = a;
        qab[1] = fmaf(-mu, a, bq[0]);
    }
}

// ---------------- choice = softmax( relu(bn(q))[nbr] @ ksum^T ) ---------------
__global__ void choice_kernel(const int* __restrict__ nbr, const float* __restrict__ q,
    const float* __restrict__ qab, const float* __restrict__ ks,
    float* __restrict__ choice)
{
    __shared__ float sks[2 * KK];
    if (threadIdx.x < 2 * KK) sks[threadIdx.x] = ks[threadIdx.x];
    __syncthreads();
    const int n = blockIdx.x * 256 + threadIdx.x;
    const float a = qab[0], b = qab[1];
    float l0 = 0.f, l1 = 0.f;
#pragma unroll
    for (int k = 0; k < KK; k++) {
        int idx = nbr[(size_t)n * KK + k];
        float qq = fmaxf(fmaf(q[idx], a, b), 0.f);
        l0 = fmaf(qq, sks[k], l0);
        l1 = fmaf(qq, sks[KK + k], l1);
    }
    float m = fmaxf(l0, l1);
    float e0 = expf(l0 - m), e1 = expf(l1 - m);
    float inv = 1.f / (e0 + e1);
    choice[(size_t)n * 2]     = e0 * inv;
    choice[(size_t)n * 2 + 1] = e1 * inv;
}

// ---------------- routed gather: round-11 proven config, fp16 out --------------
constexpr int RG_ROWS = 16;
constexpr int RG_SMEM = (2 * KK * CH + 2 * RG_ROWS + KK * RG_ROWS) * 4;

__global__ void __launch_bounds__(256) routed_gather(
    const __half2* __restrict__ vr, const int* __restrict__ nbr,
    const float* __restrict__ choice, const float* __restrict__ cb,
    __half2* __restrict__ o1)
{
    extern __shared__ float sm[];
    float* s_cb = sm;                           // 2*27*256
    float* s_ch = s_cb + 2 * KK * CH;           // 2*16
    int*   s_idx = (int*)(s_ch + 2 * RG_ROWS);  // 27*16
    const int tid = threadIdx.x;
    const int grp = tid >> 6;        // 0..3 -> rows j*4+grp
    const int c4  = tid & 63;        // channel quad
    const int n0 = blockIdx.x * RG_ROWS;

    for (int i = tid; i < 2 * KK * CH; i += 256) s_cb[i] = cb[i];
    if (tid < 2 * RG_ROWS) s_ch[tid] = choice[(size_t)n0 * 2 + tid];
    for (int i = tid; i < KK * RG_ROWS; i += 256) s_idx[i] = nbr[(size_t)n0 * KK + i];
    __syncthreads();

    float4 acc0[4], acc1[4];
#pragma unroll
    for (int j = 0; j < 4; j++) {
        acc0[j] = make_float4(0.f, 0.f, 0.f, 0.f);
        acc1[j] = make_float4(0.f, 0.f, 0.f, 0.f);
    }

    for (int k = 0; k < KK; k++) {
        const float4 w0 = reinterpret_cast<const float4*>(s_cb + k * CH)[c4];
        const float4 w1 = reinterpret_cast<const float4*>(s_cb + (KK + k) * CH)[c4];
#pragma unroll
        for (int j = 0; j < 4; j++) {
            const int r = j * 4 + grp;
            const int idx = s_idx[r * KK + k];
            const int2 raw = __ldcg(reinterpret_cast<const int2*>(
                vr + (size_t)idx * 128 + c4 * 2));
            const float2 va = __half22float2(*reinterpret_cast<const __half2*>(&raw.x));
            const float2 vb = __half22float2(*reinterpret_cast<const __half2*>(&raw.y));
            acc0[j].x = fmaf(va.x, w0.x, acc0[j].x);
            acc0[j].y = fmaf(va.y, w0.y, acc0[j].y);
            acc0[j].z = fmaf(vb.x, w0.z, acc0[j].z);
            acc0[j].w = fmaf(vb.y, w0.w, acc0[j].w);
            acc1[j].x = fmaf(va.x, w1.x, acc1[j].x);
            acc1[j].y = fmaf(va.y, w1.y, acc1[j].y);
            acc1[j].z = fmaf(vb.x, w1.z, acc1[j].z);
            acc1[j].w = fmaf(vb.y, w1.w, acc1[j].w);
        }
    }
#pragma unroll
    for (int j = 0; j < 4; j++) {
        const int r = j * 4 + grp;
        const float c0 = s_ch[2 * r], c1 = s_ch[2 * r + 1];
        float o0 = fmaf(c0, acc0[j].x, c1 * acc1[j].x);
        float o1v = fmaf(c0, acc0[j].y, c1 * acc1[j].y);
        float o2 = fmaf(c0, acc0[j].z, c1 * acc1[j].z);
        float o3 = fmaf(c0, acc0[j].w, c1 * acc1[j].w);
        const size_t base = (size_t)(n0 + r) * 128 + c4 * 2;
        o1[base]     = __floats2half2_rn(o0, o1v);
        o1[base + 1] = __floats2half2_rn(o2, o3);
    }
}

// ---------------- final: relu(bn(y)) + x, float4 vectorized ---------------------
__global__ void __launch_bounds__(256) final_kernel(
    const float4* __restrict__ y, const float4* __restrict__ x,
    const float* __restrict__ yab, float4* __restrict__ out)
{
    const int i = blockIdx.x * 256 + threadIdx.x;
    const int c4 = i & 31;
    const float4 a = reinterpret_cast<const float4*>(yab)[c4];
    const float4 b = reinterpret_cast<const float4*>(yab + C)[c4];
    const float4 yv = y[i];
    const float4 xv = x[i];
    float4 o;
    o.x = fmaxf(fmaf(yv.x, a.x, b.x), 0.f) + xv.x;
    o.y = fmaxf(fmaf(yv.y, a.y, b.y), 0.f) + xv.y;
    o.z = fmaxf(fmaf(yv.z, a.z, b.z), 0.f) + xv.z;
    o.w = fmaxf(fmaf(yv.w, a.w, b.w), 0.f) + xv.w;
    out[i] = o;
}

// ---------------- launch -------------------------------------------------------
extern "C" void kernel_launch(void* const* d_in, const int* in_sizes, int n_in,
                              void* d_out, int out_size)
{
    const float* x    = (const float*)d_in[0];
    const int*   nbr  = (const int*)  d_in[1];
    const float* Wv   = (const float*)d_in[2];
    const float* gv   = (const float*)d_in[3];
    const float* bv   = (const float*)d_in[4];
    const float* Wq   = (const float*)d_in[5];
    const float* gq   = (const float*)d_in[6];
    const float* bq   = (const float*)d_in[7];
    const float* cb   = (const float*)d_in[8];
    const float* Wout = (const float*)d_in[9];
    const float* go   = (const float*)d_in[10];
    const float* bo   = (const float*)d_in[11];
    float* out = (float*)d_out;
    const int N = in_sizes[0] / C;

    __half *pvh, *pvr, *pxh, *po1, *pWvh, *pWvl, *pWoh, *pWol;
    float *pP, *pq, *py, *ppart, *pqpart, *pvab, *pqab, *pyab, *pksum, *pchoice;
    cudaGetSymbolAddress((void**)&pvh,    g_vh);
    cudaGetSymbolAddress((void**)&pvr,    g_vr);
    cudaGetSymbolAddress((void**)&pxh,    g_xh);
    cudaGetSymbolAddress((void**)&po1,    g_o1);
    cudaGetSymbolAddress((void**)&pWvh,   g_Wvh);
    cudaGetSymbolAddress((void**)&pWvl,   g_Wvl);
    cudaGetSymbolAddress((void**)&pWoh,   g_Woh);
    cudaGetSymbolAddress((void**)&pWol,   g_Wol);
    cudaGetSymbolAddress((void**)&pP,     g_P);
    cudaGetSymbolAddress((void**)&pq,     g_q);
    cudaGetSymbolAddress((void**)&py,     g_y);
    cudaGetSymbolAddress((void**)&ppart,  g_part);
    cudaGetSymbolAddress((void**)&pqpart, g_qpart);
    cudaGetSymbolAddress((void**)&pvab,   g_vab);
    cudaGetSymbolAddress((void**)&pqab,   g_qab);
    cudaGetSymbolAddress((void**)&pyab,   g_yab);
    cudaGetSymbolAddress((void**)&pksum,  g_ksum);
    cudaGetSymbolAddress((void**)&pchoice,g_choice);

    cudaFuncSetAttribute(routed_gather,
                         cudaFuncAttributeMaxDynamicSharedMemorySize, RG_SMEM);
    cudaFuncSetAttribute((hgemm16<128, true, false>),
                         cudaFuncAttributeMaxDynamicSharedMemorySize, HG_SMEM);
    cudaFuncSetAttribute((hgemm16<256, false, false>),
                         cudaFuncAttributeMaxDynamicSharedMemorySize, HG_SMEM);

    const float invN = 1.f / (float)N;

    // weight splits + ksum (one kernel)
    prep_kernel<<<64 + MM * KK, 256>>>(Wv, Wout, cb,
        (__half2*)pWvh, (__half2*)pWvl, (__half2*)pWoh, (__half2*)pWol, pksum);
    // P = x @ Wq^T, also emits x as fp16
    p_gemm<<<N / 8, 256>>>(x, Wq, pP, (__half2*)pxh);
    // v = x @ Wv  (plain-A fp16 GEMM, split-B, fp16 out, fused column stats)
    hgemm16<128, true, false><<<dim3(N / 128, CH / 128), 256, HG_SMEM>>>(
        pxh, nullptr, pWvh, pWvl, pvh, CH, ppart);
    reduce_affine<<<CH, 256>>>(ppart, gv, bv, pvab, invN, N / 128, CH);
    // vr = relu(bn(v)) fp16
    {
        const int n2 = N * CH / 2;
        vrelu_kernel<<<n2 / 256, 256>>>(
            (const __half2*)pvh, pvab, (__half2*)pvr, n2);
    }
    // q pipeline
    q_gather<<<N / 256, 256>>>(nbr, pP, pq, pqpart);
    q_finalize<<<1, NSB>>>(pqpart, gq, bq, pqab, invN);
    choice_kernel<<<N / 256, 256>>>(nbr, pq, pqab, pksum, pchoice);
    // routed channelwise gather conv -> plain fp16 out1
    routed_gather<<<N / RG_ROWS, 256, RG_SMEM>>>(
        (const __half2*)pvr, nbr, pchoice, cb, (__half2*)po1);
    // y = out1 @ Wout (plain-A fp16 GEMM, split B, fp32 out, fused stats)
    hgemm16<256, false, false><<<dim3(N / 128, 1), 256, HG_SMEM>>>(
        po1, nullptr, pWoh, pWol, py, C, ppart);
    reduce_affine<<<C, 256>>>(ppart, go, bo, pyab, invN, N / 128, C);
    // out = relu(bn(y)) + x (float4 vectorized)
    final_kernel<<<(size_t)N * C / 4 / 256, 256>>>(
        (const float4*)py, (const float4*)x, pyab, (float4*)out);
}

// round 15
// speedup vs baseline: 1.1673x; 1.0490x over previous
#include <cuda_runtime.h>
#include <cuda_fp16.h>
#include <math.h>

#define EPSV 1e-5f

constexpr int C   = 128;
constexpr int CH  = 256;   // C*H
constexpr int KK  = 27;
constexpr int MM  = 2;
constexpr int NPTS = 131072;
constexpr int NSB = 512;   // q stat partial blocks

// ---------------- device scratch (static; no allocations allowed) --------------
__device__ __half g_vh [(size_t)NPTS * CH];   // x @ Wv (pre-BN), fp16
__device__ __half g_vr [(size_t)NPTS * CH];   // relu(bn(v)), fp16
__device__ __half g_xh [(size_t)NPTS * C];    // x fp16
__device__ __half g_o1 [(size_t)NPTS * CH];   // out1, plain fp16
__device__ __half g_Wvh[C * CH], g_Wvl[C * CH];
__device__ __half g_Woh[CH * C], g_Wol[CH * C];
__device__ __half g_cbh[MM * KK * CH];        // codebook, fp16 copy
__device__ float g_P   [(size_t)NPTS * KK];   // x @ Wq^T
__device__ float g_q   [NPTS];                // raw q (pre-BN)
__device__ float g_y   [(size_t)NPTS * C];    // out1 @ Wout (pre-BN)
__device__ float g_part[2048 * 512];          // GEMM-epilogue column-stat partials
__device__ float g_qpart[2 * NSB];            // q stat partials
__device__ float g_vab [2 * CH];              // v BN affine (a, b)
__device__ float g_qab [2];                   // q BN affine
__device__ float g_yab [2 * C];               // y BN affine
__device__ float g_ksum[MM * KK];             // cb.sum(-1)
__device__ float g_choice[(size_t)NPTS * MM];

__device__ __forceinline__ void split2(float f, __half& hi, __half& lo) {
    hi = __float2half_rn(f);
    lo = __float2half_rn(f - __half2float(hi));
}

// ---------------- prep: weight splits + ksum + fp16 cb, one kernel -------------
__global__ void __launch_bounds__(256) prep_kernel(
    const float* __restrict__ Wv, const float* __restrict__ Wout,
    const float* __restrict__ cb,
    __half2* __restrict__ Wvh, __half2* __restrict__ Wvl,
    __half2* __restrict__ Woh, __half2* __restrict__ Wol,
    float* __restrict__ ks, __half* __restrict__ cbh)
{
    const int b = blockIdx.x;
    if (b < 64) {
        const bool isWv = b < 32;
        const int i = (isWv ? b : b - 32) * 256 + threadIdx.x;  // < 8192 float4
        float4 v = (isWv ? (const float4*)Wv : (const float4*)Wout)[i];
        __half h0,l0,h1,l1,h2,l2,h3,l3;
        split2(v.x,h0,l0); split2(v.y,h1,l1); split2(v.z,h2,l2); split2(v.w,h3,l3);
        __half2* oh = isWv ? Wvh : Woh;
        __half2* ol = isWv ? Wvl : Wol;
        oh[2*i]   = __halves2half2(h0,h1); oh[2*i+1] = __halves2half2(h2,h3);
        ol[2*i]   = __halves2half2(l0,l1); ol[2*i+1] = __halves2half2(l2,l3);
    } else {
        __shared__ float sh[256];
        const int row = b - 64;   // 0..53
        const float val = cb[(size_t)row * CH + threadIdx.x];
        cbh[(size_t)row * CH + threadIdx.x] = __float2half_rn(val);  // fp16 copy
        sh[threadIdx.x] = val;
        __syncthreads();
        for (int o = 128; o; o >>= 1) {
            if (threadIdx.x < o) sh[threadIdx.x] += sh[threadIdx.x + o];
            __syncthreads();
        }
        if (threadIdx.x == 0) ks[row] = sh[0];
    }
}

// =====================================================================
// fp16 tensor-core GEMM, cp.async double-buffered, fused column stats.
// SPLIT_A=true : D = Ah*Bh + Ah*Bl + Al*Bh
// SPLIT_A=false: D = A*Bh  + A*Bl
// =====================================================================
constexpr int APITCH = 40;
constexpr int BPITCH = 136;
constexpr int HG_SMEM = (2 * 2 * 128 * APITCH + 2 * 2 * 32 * BPITCH) * 2;

__device__ __forceinline__ void cpasync16(__half* dst, const __half* src) {
    unsigned d = (unsigned)__cvta_generic_to_shared(dst);
    asm volatile("cp.async.cg.shared.global [%0], [%1], 16;\n" :: "r"(d), "l"(src));
}

template<int Kd, bool HALF_OUT, bool SPLIT_A>
__global__ void __launch_bounds__(256) hgemm16(
    const __half* __restrict__ Ahg, const __half* __restrict__ Alg,
    const __half* __restrict__ Bhg, const __half* __restrict__ Blg,
    void* __restrict__ Cout, int Ncols, float* __restrict__ part)
{
    extern __shared__ float smraw[];
    __half* As = reinterpret_cast<__half*>(smraw);
    __half* Bs = As + 2 * 2 * 128 * APITCH;

    const int tid  = threadIdx.x;
    const int warp = tid >> 5, lane = tid & 31;
    const int wm = warp >> 2;
    const int wn = warp & 3;
    const int rowBase = blockIdx.x * 128;
    const int colBase = blockIdx.y * 128;
    constexpr int KT = Kd / 32;

    float acc[4][4][4];
#pragma unroll
    for (int i = 0; i < 4; i++)
#pragma unroll
        for (int j = 0; j < 4; j++)
#pragma unroll
            for (int f = 0; f < 4; f++) acc[i][j][f] = 0.f;

    auto load_stage = [&](int s, int k0) {
        __half* Ah_s = As + (s * 2 + 0) * (128 * APITCH);
        __half* Al_s = As + (s * 2 + 1) * (128 * APITCH);
        __half* Bh_s = Bs + (s * 2 + 0) * (32 * BPITCH);
        __half* Bl_s = Bs + (s * 2 + 1) * (32 * BPITCH);
#pragma unroll
        for (int it = 0; it < 2; it++) {
            int idx = it * 256 + tid;
            int r = idx >> 2, q = idx & 3;
            size_t ga = (size_t)(rowBase + r) * Kd + k0 + q * 8;
            cpasync16(&Ah_s[r * APITCH + q * 8], &Ahg[ga]);
            if constexpr (SPLIT_A)
                cpasync16(&Al_s[r * APITCH + q * 8], &Alg[ga]);
            int rb = idx >> 4, qb = idx & 15;
            size_t gb = (size_t)(k0 + rb) * Ncols + colBase + qb * 8;
            cpasync16(&Bh_s[rb * BPITCH + qb * 8], &Bhg[gb]);
            cpasync16(&Bl_s[rb * BPITCH + qb * 8], &Blg[gb]);
        }
        asm volatile("cp.async.commit_group;\n" ::);
    };

    load_stage(0, 0);

    for (int kt = 0; kt < KT; kt++) {
        if (kt + 1 < KT) {
            load_stage((kt + 1) & 1, (kt + 1) * 32);
            asm volatile("cp.async.wait_group 1;\n" ::);
        } else {
            asm volatile("cp.async.wait_group 0;\n" ::);
        }
        __syncthreads();

        const int s = kt & 1;
        const __half* Ah_s = As + (s * 2 + 0) * (128 * APITCH);
        const __half* Al_s = As + (s * 2 + 1) * (128 * APITCH);
        const __half* Bh_s = Bs + (s * 2 + 0) * (32 * BPITCH);
        const __half* Bl_s = Bs + (s * 2 + 1) * (32 * BPITCH);

#pragma unroll
        for (int ks = 0; ks < 32; ks += 16) {
            unsigned ah[4][4], al[4][4];
#pragma unroll
            for (int mt = 0; mt < 4; mt++) {
                int row = wm * 64 + mt * 16 + (lane & 15);
                int col = ks + (lane >> 4) * 8;
                unsigned aH = (unsigned)__cvta_generic_to_shared(&Ah_s[row * APITCH + col]);
                asm volatile("ldmatrix.sync.aligned.m8n8.x4.shared.b16 {%0,%1,%2,%3}, [%4];"
                    : "=r"(ah[mt][0]),"=r"(ah[mt][1]),"=r"(ah[mt][2]),"=r"(ah[mt][3]) : "r"(aH));
                if constexpr (SPLIT_A) {
                    unsigned aL = (unsigned)__cvta_generic_to_shared(&Al_s[row * APITCH + col]);
                    asm volatile("ldmatrix.sync.aligned.m8n8.x4.shared.b16 {%0,%1,%2,%3}, [%4];"
                        : "=r"(al[mt][0]),"=r"(al[mt][1]),"=r"(al[mt][2]),"=r"(al[mt][3]) : "r"(aL));
                }
            }
            unsigned bh[4][2], bl[4][2];
#pragma unroll
            for (int pr = 0; pr < 2; pr++) {
                int krow = ks + (lane & 15);
                int col = wn * 32 + pr * 16 + (lane >> 4) * 8;
                unsigned aH = (unsigned)__cvta_generic_to_shared(&Bh_s[krow * BPITCH + col]);
                unsigned aL = (unsigned)__cvta_generic_to_shared(&Bl_s[krow * BPITCH + col]);
                asm volatile("ldmatrix.sync.aligned.m8n8.x4.trans.shared.b16 {%0,%1,%2,%3}, [%4];"
                    : "=r"(bh[pr*2][0]),"=r"(bh[pr*2][1]),"=r"(bh[pr*2+1][0]),"=r"(bh[pr*2+1][1]) : "r"(aH));
                asm volatile("ldmatrix.sync.aligned.m8n8.x4.trans.shared.b16 {%0,%1,%2,%3}, [%4];"
                    : "=r"(bl[pr*2][0]),"=r"(bl[pr*2][1]),"=r"(bl[pr*2+1][0]),"=r"(bl[pr*2+1][1]) : "r"(aL));
            }
#pragma unroll
            for (int mt = 0; mt < 4; mt++)
#pragma unroll
                for (int nt = 0; nt < 4; nt++) {
                    float* d = acc[mt][nt];
#define MMA(Af, Bf) \
    asm volatile("mma.sync.aligned.m16n8k16.row.col.f32.f16.f16.f32 " \
        "{%0,%1,%2,%3}, {%4,%5,%6,%7}, {%8,%9}, {%0,%1,%2,%3};" \
        : "+f"(d[0]),"+f"(d[1]),"+f"(d[2]),"+f"(d[3]) \
        : "r"(Af[0]),"r"(Af[1]),"r"(Af[2]),"r"(Af[3]), "r"(Bf[0]),"r"(Bf[1]))
                    MMA(ah[mt], bh[nt]);
                    MMA(ah[mt], bl[nt]);
                    if constexpr (SPLIT_A) { MMA(al[mt], bh[nt]); }
#undef MMA
                }
        }
        __syncthreads();
    }

    // ---- output stores ----
    const int g = lane >> 2, tg = lane & 3;
#pragma unroll
    for (int mt = 0; mt < 4; mt++)
#pragma unroll
        for (int nt = 0; nt < 4; nt++) {
            size_t row = (size_t)rowBase + wm * 64 + mt * 16 + g;
            int col = colBase + wn * 32 + nt * 8 + tg * 2;
            float* d = acc[mt][nt];
            if constexpr (HALF_OUT) {
                __half* Cm = (__half*)Cout;
                *reinterpret_cast<__half2*>(&Cm[row * Ncols + col]) =
                    __floats2half2_rn(d[0], d[1]);
                *reinterpret_cast<__half2*>(&Cm[(row + 8) * Ncols + col]) =
                    __floats2half2_rn(d[2], d[3]);
            } else {
                float* Cm = (float*)Cout;
                *reinterpret_cast<float2*>(&Cm[row * Ncols + col]) =
                    make_float2(d[0], d[1]);
                *reinterpret_cast<float2*>(&Cm[(row + 8) * Ncols + col]) =
                    make_float2(d[2], d[3]);
            }
        }

    // ---- fused column stats ----
#pragma unroll
    for (int nt = 0; nt < 4; nt++) {
        float a0 = 0.f, a1 = 0.f, b0 = 0.f, b1 = 0.f;
#pragma unroll
        for (int mt = 0; mt < 4; mt++) {
            float* d = acc[mt][nt];
            a0 += d[0] + d[2];
            a1 += d[1] + d[3];
            b0 = fmaf(d[0], d[0], fmaf(d[2], d[2], b0));
            b1 = fmaf(d[1], d[1], fmaf(d[3], d[3], b1));
        }
#pragma unroll
        for (int o = 4; o <= 16; o <<= 1) {
            a0 += __shfl_xor_sync(0xFFFFFFFFu, a0, o);
            a1 += __shfl_xor_sync(0xFFFFFFFFu, a1, o);
            b0 += __shfl_xor_sync(0xFFFFFFFFu, b0, o);
            b1 += __shfl_xor_sync(0xFFFFFFFFu, b1, o);
        }
        if ((lane >> 2) == 0) {
            float* pb = part +
                ((size_t)(blockIdx.y * gridDim.x + blockIdx.x) * 2 + wm) * 256;
            int c0 = wn * 32 + nt * 8 + lane * 2;
            pb[c0]           = a0;
            pb[c0 + 1]       = a1;
            pb[128 + c0]     = b0;
            pb[128 + c0 + 1] = b1;
        }
    }
}

// ---------------- generic affine reduce over GEMM partials --------------------
__global__ void reduce_affine(const float* __restrict__ part,
    const float* __restrict__ gg, const float* __restrict__ bb,
    float* __restrict__ ab, float invN, int nbx, int CC)
{
    const int c = blockIdx.x;
    const int y = c >> 7, cc = c & 127;
    float s = 0.f, s2 = 0.f;
    for (int b = threadIdx.x; b < nbx * 2; b += 256) {
        const float* p = part + ((size_t)(y * nbx + (b >> 1)) * 2 + (b & 1)) * 256;
        s += p[cc]; s2 += p[128 + cc];
    }
    __shared__ float shm[512];
    shm[threadIdx.x] = s; shm[256 + threadIdx.x] = s2;
    __syncthreads();
    for (int o = 128; o; o >>= 1) {
        if (threadIdx.x < o) {
            shm[threadIdx.x] += shm[threadIdx.x + o];
            shm[256 + threadIdx.x] += shm[256 + threadIdx.x + o];
        }
        __syncthreads();
    }
    if (threadIdx.x == 0) {
        float mu  = shm[0] * invN;
        float var = fmaf(-mu, mu, shm[256] * invN);
        float a = gg[c] * rsqrtf(var + EPSV);
        ab[c] = a;
        ab[CC + c] = fmaf(-mu, a, bb[c]);
    }
}

// ---------------- P = x @ Wq^T + fused fp16 cast of x --------------------------
__global__ void __launch_bounds__(256) p_gemm(
    const float* __restrict__ x, const float* __restrict__ Wq,
    float* __restrict__ P, __half2* __restrict__ xh)
{
    __shared__ float wqs[KK * C];
    __shared__ float red[8][KK * 32];
    for (int i = threadIdx.x; i < KK * C; i += 256) wqs[i] = Wq[i];
    __syncthreads();
    const int warp = threadIdx.x >> 5, lane = threadIdx.x & 31;
    const int row = blockIdx.x * 8 + warp;
    float4 xv = reinterpret_cast<const float4*>(x + (size_t)row * C)[lane];

    {
        const size_t base = (size_t)row * 64 + lane * 2;
        xh[base]     = __floats2half2_rn(xv.x, xv.y);
        xh[base + 1] = __floats2half2_rn(xv.z, xv.w);
    }

    float part[KK];
#pragma unroll
    for (int k = 0; k < KK; k++) {
        float4 w = reinterpret_cast<const float4*>(wqs + k * C)[lane];
        part[k] = xv.x * w.x + xv.y * w.y + xv.z * w.z + xv.w * w.w;
    }
#pragma unroll
    for (int k = 0; k < KK; k++) red[warp][lane * KK + k] = part[k];
    __syncwarp();
    if (lane < KK) {
        float s = 0.f;
#pragma unroll
        for (int j = 0; j < 32; j++) s += red[warp][j * KK + lane];
        P[(size_t)row * KK + lane] = s;
    }
}

// ---------------- vr = relu(bn(v)) as fp16 -------------------------------------
__global__ void __launch_bounds__(256) vrelu_kernel(
    const __half2* __restrict__ vh, const float* __restrict__ vab,
    __half2* __restrict__ vr, int n2)
{
    int i = blockIdx.x * 256 + threadIdx.x;
    if (i >= n2) return;
    int c2 = i & 127;
    float2 a = reinterpret_cast<const float2*>(vab)[c2];
    float2 b = reinterpret_cast<const float2*>(vab + CH)[c2];
    float2 v = __half22float2(vh[i]);
    vr[i] = __floats2half2_rn(fmaxf(fmaf(v.x, a.x, b.x), 0.f),
                              fmaxf(fmaf(v.y, a.y, b.y), 0.f));
}

// ---------------- q[n] = sum_k P[nbr[n,k], k] + stats -------------------------
__global__ void q_gather(const int* __restrict__ nbr, const float* __restrict__ P,
                         float* __restrict__ q, float* __restrict__ qpart)
{
    const int n = blockIdx.x * 256 + threadIdx.x;
    float s = 0.f;
#pragma unroll
    for (int k = 0; k < KK; k++) {
        int idx = nbr[(size_t)n * KK + k];
        s += P[(size_t)idx * KK + k];
    }
    q[n] = s;
    __shared__ float sh[512];
    sh[threadIdx.x] = s;
    sh[256 + threadIdx.x] = s * s;
    __syncthreads();
    for (int o = 128; o; o >>= 1) {
        if (threadIdx.x < o) {
            sh[threadIdx.x] += sh[threadIdx.x + o];
            sh[256 + threadIdx.x] += sh[256 + threadIdx.x + o];
        }
        __syncthreads();
    }
    if (threadIdx.x == 0) {
        qpart[blockIdx.x] = sh[0];
        qpart[NSB + blockIdx.x] = sh[256];
    }
}

__global__ void q_finalize(const float* __restrict__ qpart,
    const float* __restrict__ gq, const float* __restrict__ bq,
    float* __restrict__ qab, float invN)
{
    __shared__ float sh[2 * NSB];
    sh[threadIdx.x] = qpart[threadIdx.x];
    sh[NSB + threadIdx.x] = qpart[NSB + threadIdx.x];
    __syncthreads();
    for (int o = NSB / 2; o; o >>= 1) {
        if (threadIdx.x < o) {
            sh[threadIdx.x] += sh[threadIdx.x + o];
            sh[NSB + threadIdx.x] += sh[NSB + threadIdx.x + o];
        }
        __syncthreads();
    }
    if (threadIdx.x == 0) {
        float mu  = sh[0] * invN;
        float var = fmaf(-mu, mu, sh[NSB] * invN);
        float a = gq[0] * rsqrtf(var + EPSV);
        qab[0] = a;
        qab[1] = fmaf(-mu, a, bq[0]);
    }
}

// ---------------- choice = softmax( relu(bn(q))[nbr] @ ksum^T ) ---------------
__global__ void choice_kernel(const int* __restrict__ nbr, const float* __restrict__ q,
    const float* __restrict__ qab, const float* __restrict__ ks,
    float* __restrict__ choice)
{
    __shared__ float sks[2 * KK];
    if (threadIdx.x < 2 * KK) sks[threadIdx.x] = ks[threadIdx.x];
    __syncthreads();
    const int n = blockIdx.x * 256 + threadIdx.x;
    const float a = qab[0], b = qab[1];
    float l0 = 0.f, l1 = 0.f;
#pragma unroll
    for (int k = 0; k < KK; k++) {
        int idx = nbr[(size_t)n * KK + k];
        float qq = fmaxf(fmaf(q[idx], a, b), 0.f);
        l0 = fmaf(qq, sks[k], l0);
        l1 = fmaf(qq, sks[KK + k], l1);
    }
    float m = fmaxf(l0, l1);
    float e0 = expf(l0 - m), e1 = expf(l1 - m);
    float inv = 1.f / (e0 + e1);
    choice[(size_t)n * 2]     = e0 * inv;
    choice[(size_t)n * 2 + 1] = e1 * inv;
}

// ---------------- routed gather: fp16 codebook in smem -> 7 blocks/SM ----------
// smem = 2*27*256*2 (fp16 cb) + (2*16)*4 + (27*16)*4 = 29504 B
constexpr int RG_ROWS = 16;
constexpr int RG_SMEM = 2 * KK * CH * 2 + (2 * RG_ROWS + KK * RG_ROWS) * 4;

__global__ void __launch_bounds__(256) routed_gather(
    const __half2* __restrict__ vr, const int* __restrict__ nbr,
    const float* __restrict__ choice, const __half* __restrict__ cbh,
    __half2* __restrict__ o1)
{
    extern __shared__ float sm[];
    __half* s_cb = reinterpret_cast<__half*>(sm);      // 2*27*256 halves
    float* s_ch = sm + (2 * KK * CH * 2) / 4;          // 2*16 floats
    int*   s_idx = (int*)(s_ch + 2 * RG_ROWS);         // 27*16 ints
    const int tid = threadIdx.x;
    const int grp = tid >> 6;        // 0..3 -> rows j*4+grp
    const int c4  = tid & 63;        // channel quad
    const int n0 = blockIdx.x * RG_ROWS;

    // fill cb (fp16, 27648 B = 1728 float4)
    for (int i = tid; i < (2 * KK * CH * 2) / 16; i += 256)
        reinterpret_cast<float4*>(s_cb)[i] =
            reinterpret_cast<const float4*>(cbh)[i];
    if (tid < 2 * RG_ROWS) s_ch[tid] = choice[(size_t)n0 * 2 + tid];
    for (int i = tid; i < KK * RG_ROWS; i += 256) s_idx[i] = nbr[(size_t)n0 * KK + i];
    __syncthreads();

    const __half2* cb2 = reinterpret_cast<const __half2*>(s_cb);

    float4 acc0[4], acc1[4];
#pragma unroll
    for (int j = 0; j < 4; j++) {
        acc0[j] = make_float4(0.f, 0.f, 0.f, 0.f);
        acc1[j] = make_float4(0.f, 0.f, 0.f, 0.f);
    }

    for (int k = 0; k < KK; k++) {
        // channels [c4*4, c4*4+4): two half2 per kernel, 8B LDS each
        const int2 rw0 = *reinterpret_cast<const int2*>(cb2 + k * 128 + c4 * 2);
        const int2 rw1 = *reinterpret_cast<const int2*>(cb2 + (KK + k) * 128 + c4 * 2);
        const float2 w0a = __half22float2(*reinterpret_cast<const __half2*>(&rw0.x));
        const float2 w0b = __half22float2(*reinterpret_cast<const __half2*>(&rw0.y));
        const float2 w1a = __half22float2(*reinterpret_cast<const __half2*>(&rw1.x));
        const float2 w1b = __half22float2(*reinterpret_cast<const __half2*>(&rw1.y));
#pragma unroll
        for (int j = 0; j < 4; j++) {
            const int r = j * 4 + grp;
            const int idx = s_idx[r * KK + k];
            const int2 raw = __ldcg(reinterpret_cast<const int2*>(
                vr + (size_t)idx * 128 + c4 * 2));
            const float2 va = __half22float2(*reinterpret_cast<const __half2*>(&raw.x));
            const float2 vb = __half22float2(*reinterpret_cast<const __half2*>(&raw.y));
            acc0[j].x = fmaf(va.x, w0a.x, acc0[j].x);
            acc0[j].y = fmaf(va.y, w0a.y, acc0[j].y);
            acc0[j].z = fmaf(vb.x, w0b.x, acc0[j].z);
            acc0[j].w = fmaf(vb.y, w0b.y, acc0[j].w);
            acc1[j].x = fmaf(va.x, w1a.x, acc1[j].x);
            acc1[j].y = fmaf(va.y, w1a.y, acc1[j].y);
            acc1[j].z = fmaf(vb.x, w1b.x, acc1[j].z);
            acc1[j].w = fmaf(vb.y, w1b.y, acc1[j].w);
        }
    }
#pragma unroll
    for (int j = 0; j < 4; j++) {
        const int r = j * 4 + grp;
        const float c0 = s_ch[2 * r], c1 = s_ch[2 * r + 1];
        float o0 = fmaf(c0, acc0[j].x, c1 * acc1[j].x);
        float o1v = fmaf(c0, acc0[j].y, c1 * acc1[j].y);
        float o2 = fmaf(c0, acc0[j].z, c1 * acc1[j].z);
        float o3 = fmaf(c0, acc0[j].w, c1 * acc1[j].w);
        const size_t base = (size_t)(n0 + r) * 128 + c4 * 2;
        o1[base]     = __floats2half2_rn(o0, o1v);
        o1[base + 1] = __floats2half2_rn(o2, o3);
    }
}

// ---------------- final: relu(bn(y)) + x, float4 vectorized ---------------------
__global__ void __launch_bounds__(256) final_kernel(
    const float4* __restrict__ y, const float4* __restrict__ x,
    const float* __restrict__ yab, float4* __restrict__ out)
{
    const int i = blockIdx.x * 256 + threadIdx.x;
    const int c4 = i & 31;
    const float4 a = reinterpret_cast<const float4*>(yab)[c4];
    const float4 b = reinterpret_cast<const float4*>(yab + C)[c4];
    const float4 yv = y[i];
    const float4 xv = x[i];
    float4 o;
    o.x = fmaxf(fmaf(yv.x, a.x, b.x), 0.f) + xv.x;
    o.y = fmaxf(fmaf(yv.y, a.y, b.y), 0.f) + xv.y;
    o.z = fmaxf(fmaf(yv.z, a.z, b.z), 0.f) + xv.z;
    o.w = fmaxf(fmaf(yv.w, a.w, b.w), 0.f) + xv.w;
    out[i] = o;
}

// ---------------- launch -------------------------------------------------------
extern "C" void kernel_launch(void* const* d_in, const int* in_sizes, int n_in,
                              void* d_out, int out_size)
{
    const float* x    = (const float*)d_in[0];
    const int*   nbr  = (const int*)  d_in[1];
    const float* Wv   = (const float*)d_in[2];
    const float* gv   = (const float*)d_in[3];
    const float* bv   = (const float*)d_in[4];
    const float* Wq   = (const float*)d_in[5];
    const float* gq   = (const float*)d_in[6];
    const float* bq   = (const float*)d_in[7];
    const float* cb   = (const float*)d_in[8];
    const float* Wout = (const float*)d_in[9];
    const float* go   = (const float*)d_in[10];
    const float* bo   = (const float*)d_in[11];
    float* out = (float*)d_out;
    const int N = in_sizes[0] / C;

    __half *pvh, *pvr, *pxh, *po1, *pWvh, *pWvl, *pWoh, *pWol, *pcbh;
    float *pP, *pq, *py, *ppart, *pqpart, *pvab, *pqab, *pyab, *pksum, *pchoice;
    cudaGetSymbolAddress((void**)&pvh,    g_vh);
    cudaGetSymbolAddress((void**)&pvr,    g_vr);
    cudaGetSymbolAddress((void**)&pxh,    g_xh);
    cudaGetSymbolAddress((void**)&po1,    g_o1);
    cudaGetSymbolAddress((void**)&pWvh,   g_Wvh);
    cudaGetSymbolAddress((void**)&pWvl,   g_Wvl);
    cudaGetSymbolAddress((void**)&pWoh,   g_Woh);
    cudaGetSymbolAddress((void**)&pWol,   g_Wol);
    cudaGetSymbolAddress((void**)&pcbh,   g_cbh);
    cudaGetSymbolAddress((void**)&pP,     g_P);
    cudaGetSymbolAddress((void**)&pq,     g_q);
    cudaGetSymbolAddress((void**)&py,     g_y);
    cudaGetSymbolAddress((void**)&ppart,  g_part);
    cudaGetSymbolAddress((void**)&pqpart, g_qpart);
    cudaGetSymbolAddress((void**)&pvab,   g_vab);
    cudaGetSymbolAddress((void**)&pqab,   g_qab);
    cudaGetSymbolAddress((void**)&pyab,   g_yab);
    cudaGetSymbolAddress((void**)&pksum,  g_ksum);
    cudaGetSymbolAddress((void**)&pchoice,g_choice);

    cudaFuncSetAttribute(routed_gather,
                         cudaFuncAttributeMaxDynamicSharedMemorySize, RG_SMEM);
    cudaFuncSetAttribute((hgemm16<128, true, false>),
                         cudaFuncAttributeMaxDynamicSharedMemorySize, HG_SMEM);
    cudaFuncSetAttribute((hgemm16<256, false, false>),
                         cudaFuncAttributeMaxDynamicSharedMemorySize, HG_SMEM);

    const float invN = 1.f / (float)N;

    // weight splits + ksum + fp16 codebook (one kernel)
    prep_kernel<<<64 + MM * KK, 256>>>(Wv, Wout, cb,
        (__half2*)pWvh, (__half2*)pWvl, (__half2*)pWoh, (__half2*)pWol,
        pksum, pcbh);
    // P = x @ Wq^T, also emits x as fp16
    p_gemm<<<N / 8, 256>>>(x, Wq, pP, (__half2*)pxh);
    // v = x @ Wv  (plain-A fp16 GEMM, split-B, fp16 out, fused column stats)
    hgemm16<128, true, false><<<dim3(N / 128, CH / 128), 256, HG_SMEM>>>(
        pxh, nullptr, pWvh, pWvl, pvh, CH, ppart);
    reduce_affine<<<CH, 256>>>(ppart, gv, bv, pvab, invN, N / 128, CH);
    // vr = relu(bn(v)) fp16
    {
        const int n2 = N * CH / 2;
        vrelu_kernel<<<n2 / 256, 256>>>(
            (const __half2*)pvh, pvab, (__half2*)pvr, n2);
    }
    // q pipeline
    q_gather<<<N / 256, 256>>>(nbr, pP, pq, pqpart);
    q_finalize<<<1, NSB>>>(pqpart, gq, bq, pqab, invN);
    choice_kernel<<<N / 256, 256>>>(nbr, pq, pqab, pksum, pchoice);
    // routed channelwise gather conv (fp16 codebook, 7 blocks/SM) -> fp16 out1
    routed_gather<<<N / RG_ROWS, 256, RG_SMEM>>>(
        (const __half2*)pvr, nbr, pchoice, pcbh, (__half2*)po1);
    // y = out1 @ Wout (plain-A fp16 GEMM, split B, fp32 out, fused stats)
    hgemm16<256, false, false><<<dim3(N / 128, 1), 256, HG_SMEM>>>(
        po1, nullptr, pWoh, pWol, py, C, ppart);
    reduce_affine<<<C, 256>>>(ppart, go, bo, pyab, invN, N / 128, C);
    // out = relu(bn(y)) + x (float4 vectorized)
    final_kernel<<<(size_t)N * C / 4 / 256, 256>>>(
        (const float4*)py, (const float4*)x, pyab, (float4*)out);
}

// round 16
// speedup vs baseline: 1.2218x; 1.0467x over previous
#include <cuda_runtime.h>
#include <cuda_fp16.h>
#include <math.h>

#define EPSV 1e-5f

constexpr int C   = 128;
constexpr int CH  = 256;   // C*H
constexpr int KK  = 27;
constexpr int MM  = 2;
constexpr int NPTS = 131072;
constexpr int NSB = 512;   // q stat partial blocks

// ---------------- device scratch (static; no allocations allowed) --------------
__device__ __half g_vh [(size_t)NPTS * CH];   // x @ Wv (pre-BN), fp16
__device__ __half g_vr [(size_t)NPTS * CH];   // relu(bn(v)), fp16
__device__ __half g_xh [(size_t)NPTS * C];    // x fp16
__device__ __half g_o1 [(size_t)NPTS * CH];   // out1, plain fp16
__device__ __half g_Wvh[C * CH];              // Wv fp16
__device__ __half g_Woh[CH * C];              // Wout fp16
__device__ __half g_cbh[MM * KK * CH];        // codebook, fp16 copy
__device__ float g_P   [(size_t)NPTS * KK];   // x @ Wq^T
__device__ float g_q   [NPTS];                // raw q (pre-BN)
__device__ float g_y   [(size_t)NPTS * C];    // out1 @ Wout (pre-BN)
__device__ float g_part[2048 * 512];          // GEMM-epilogue column-stat partials
__device__ float g_qpart[2 * NSB];            // q stat partials
__device__ float g_vab [2 * CH];              // v BN affine (a, b)
__device__ float g_qab [2];                   // q BN affine
__device__ float g_yab [2 * C];               // y BN affine
__device__ float g_ksum[MM * KK];             // cb.sum(-1)
__device__ float g_choice[(size_t)NPTS * MM];

// ---------------- prep: weight fp16 casts + ksum + fp16 cb ---------------------
__global__ void __launch_bounds__(256) prep_kernel(
    const float* __restrict__ Wv, const float* __restrict__ Wout,
    const float* __restrict__ cb,
    __half2* __restrict__ Wvh, __half2* __restrict__ Woh,
    float* __restrict__ ks, __half* __restrict__ cbh)
{
    const int b = blockIdx.x;
    if (b < 64) {
        const bool isWv = b < 32;
        const int i = (isWv ? b : b - 32) * 256 + threadIdx.x;  // < 8192 float4
        float4 v = (isWv ? (const float4*)Wv : (const float4*)Wout)[i];
        __half2* oh = isWv ? Wvh : Woh;
        oh[2*i]   = __floats2half2_rn(v.x, v.y);
        oh[2*i+1] = __floats2half2_rn(v.z, v.w);
    } else {
        __shared__ float sh[256];
        const int row = b - 64;   // 0..53
        const float val = cb[(size_t)row * CH + threadIdx.x];
        cbh[(size_t)row * CH + threadIdx.x] = __float2half_rn(val);
        sh[threadIdx.x] = val;
        __syncthreads();
        for (int o = 128; o; o >>= 1) {
            if (threadIdx.x < o) sh[threadIdx.x] += sh[threadIdx.x + o];
            __syncthreads();
        }
        if (threadIdx.x == 0) ks[row] = sh[0];
    }
}

// =====================================================================
// plain fp16 tensor-core GEMM (single MMA), cp.async double-buffered,
// fused column stats.  D = A * B, fp32 accumulate.
// =====================================================================
constexpr int APITCH = 40;
constexpr int BPITCH = 136;
constexpr int HG_SMEM = (2 * 128 * APITCH + 2 * 32 * BPITCH) * 2;

__device__ __forceinline__ void cpasync16(__half* dst, const __half* src) {
    unsigned d = (unsigned)__cvta_generic_to_shared(dst);
    asm volatile("cp.async.cg.shared.global [%0], [%1], 16;\n" :: "r"(d), "l"(src));
}

template<int Kd, bool HALF_OUT>
__global__ void __launch_bounds__(256) hgemm16(
    const __half* __restrict__ Ahg, const __half* __restrict__ Bhg,
    void* __restrict__ Cout, int Ncols, float* __restrict__ part)
{
    extern __shared__ float smraw[];
    __half* As = reinterpret_cast<__half*>(smraw);           // [2][128*APITCH]
    __half* Bs = As + 2 * 128 * APITCH;                      // [2][32*BPITCH]

    const int tid  = threadIdx.x;
    const int warp = tid >> 5, lane = tid & 31;
    const int wm = warp >> 2;
    const int wn = warp & 3;
    const int rowBase = blockIdx.x * 128;
    const int colBase = blockIdx.y * 128;
    constexpr int KT = Kd / 32;

    float acc[4][4][4];
#pragma unroll
    for (int i = 0; i < 4; i++)
#pragma unroll
        for (int j = 0; j < 4; j++)
#pragma unroll
            for (int f = 0; f < 4; f++) acc[i][j][f] = 0.f;

    auto load_stage = [&](int s, int k0) {
        __half* Ah_s = As + s * (128 * APITCH);
        __half* Bh_s = Bs + s * (32 * BPITCH);
#pragma unroll
        for (int it = 0; it < 2; it++) {
            int idx = it * 256 + tid;
            int r = idx >> 2, q = idx & 3;
            size_t ga = (size_t)(rowBase + r) * Kd + k0 + q * 8;
            cpasync16(&Ah_s[r * APITCH + q * 8], &Ahg[ga]);
            int rb = idx >> 4, qb = idx & 15;
            size_t gb = (size_t)(k0 + rb) * Ncols + colBase + qb * 8;
            cpasync16(&Bh_s[rb * BPITCH + qb * 8], &Bhg[gb]);
        }
        asm volatile("cp.async.commit_group;\n" ::);
    };

    load_stage(0, 0);

    for (int kt = 0; kt < KT; kt++) {
        if (kt + 1 < KT) {
            load_stage((kt + 1) & 1, (kt + 1) * 32);
            asm volatile("cp.async.wait_group 1;\n" ::);
        } else {
            asm volatile("cp.async.wait_group 0;\n" ::);
        }
        __syncthreads();

        const int s = kt & 1;
        const __half* Ah_s = As + s * (128 * APITCH);
        const __half* Bh_s = Bs + s * (32 * BPITCH);

#pragma unroll
        for (int ks = 0; ks < 32; ks += 16) {
            unsigned ah[4][4];
#pragma unroll
            for (int mt = 0; mt < 4; mt++) {
                int row = wm * 64 + mt * 16 + (lane & 15);
                int col = ks + (lane >> 4) * 8;
                unsigned aH = (unsigned)__cvta_generic_to_shared(&Ah_s[row * APITCH + col]);
                asm volatile("ldmatrix.sync.aligned.m8n8.x4.shared.b16 {%0,%1,%2,%3}, [%4];"
                    : "=r"(ah[mt][0]),"=r"(ah[mt][1]),"=r"(ah[mt][2]),"=r"(ah[mt][3]) : "r"(aH));
            }
            unsigned bh[4][2];
#pragma unroll
            for (int pr = 0; pr < 2; pr++) {
                int krow = ks + (lane & 15);
                int col = wn * 32 + pr * 16 + (lane >> 4) * 8;
                unsigned aH = (unsigned)__cvta_generic_to_shared(&Bh_s[krow * BPITCH + col]);
                asm volatile("ldmatrix.sync.aligned.m8n8.x4.trans.shared.b16 {%0,%1,%2,%3}, [%4];"
                    : "=r"(bh[pr*2][0]),"=r"(bh[pr*2][1]),"=r"(bh[pr*2+1][0]),"=r"(bh[pr*2+1][1]) : "r"(aH));
            }
#pragma unroll
            for (int mt = 0; mt < 4; mt++)
#pragma unroll
                for (int nt = 0; nt < 4; nt++) {
                    float* d = acc[mt][nt];
                    asm volatile("mma.sync.aligned.m16n8k16.row.col.f32.f16.f16.f32 "
                        "{%0,%1,%2,%3}, {%4,%5,%6,%7}, {%8,%9}, {%0,%1,%2,%3};"
                        : "+f"(d[0]),"+f"(d[1]),"+f"(d[2]),"+f"(d[3])
                        : "r"(ah[mt][0]),"r"(ah[mt][1]),"r"(ah[mt][2]),"r"(ah[mt][3]),
                          "r"(bh[nt][0]),"r"(bh[nt][1]));
                }
        }
        __syncthreads();
    }

    // ---- output stores ----
    const int g = lane >> 2, tg = lane & 3;
#pragma unroll
    for (int mt = 0; mt < 4; mt++)
#pragma unroll
        for (int nt = 0; nt < 4; nt++) {
            size_t row = (size_t)rowBase + wm * 64 + mt * 16 + g;
            int col = colBase + wn * 32 + nt * 8 + tg * 2;
            float* d = acc[mt][nt];
            if constexpr (HALF_OUT) {
                __half* Cm = (__half*)Cout;
                *reinterpret_cast<__half2*>(&Cm[row * Ncols + col]) =
                    __floats2half2_rn(d[0], d[1]);
                *reinterpret_cast<__half2*>(&Cm[(row + 8) * Ncols + col]) =
                    __floats2half2_rn(d[2], d[3]);
            } else {
                float* Cm = (float*)Cout;
                *reinterpret_cast<float2*>(&Cm[row * Ncols + col]) =
                    make_float2(d[0], d[1]);
                *reinterpret_cast<float2*>(&Cm[(row + 8) * Ncols + col]) =
                    make_float2(d[2], d[3]);
            }
        }

    // ---- fused column stats ----
#pragma unroll
    for (int nt = 0; nt < 4; nt++) {
        float a0 = 0.f, a1 = 0.f, b0 = 0.f, b1 = 0.f;
#pragma unroll
        for (int mt = 0; mt < 4; mt++) {
            float* d = acc[mt][nt];
            a0 += d[0] + d[2];
            a1 += d[1] + d[3];
            b0 = fmaf(d[0], d[0], fmaf(d[2], d[2], b0));
            b1 = fmaf(d[1], d[1], fmaf(d[3], d[3], b1));
        }
#pragma unroll
        for (int o = 4; o <= 16; o <<= 1) {
            a0 += __shfl_xor_sync(0xFFFFFFFFu, a0, o);
            a1 += __shfl_xor_sync(0xFFFFFFFFu, a1, o);
            b0 += __shfl_xor_sync(0xFFFFFFFFu, b0, o);
            b1 += __shfl_xor_sync(0xFFFFFFFFu, b1, o);
        }
        if ((lane >> 2) == 0) {
            float* pb = part +
                ((size_t)(blockIdx.y * gridDim.x + blockIdx.x) * 2 + wm) * 256;
            int c0 = wn * 32 + nt * 8 + lane * 2;
            pb[c0]           = a0;
            pb[c0 + 1]       = a1;
            pb[128 + c0]     = b0;
            pb[128 + c0 + 1] = b1;
        }
    }
}

// ---------------- generic affine reduce over GEMM partials --------------------
__global__ void reduce_affine(const float* __restrict__ part,
    const float* __restrict__ gg, const float* __restrict__ bb,
    float* __restrict__ ab, float invN, int nbx, int CC)
{
    const int c = blockIdx.x;
    const int y = c >> 7, cc = c & 127;
    float s = 0.f, s2 = 0.f;
    for (int b = threadIdx.x; b < nbx * 2; b += 256) {
        const float* p = part + ((size_t)(y * nbx + (b >> 1)) * 2 + (b & 1)) * 256;
        s += p[cc]; s2 += p[128 + cc];
    }
    __shared__ float shm[512];
    shm[threadIdx.x] = s; shm[256 + threadIdx.x] = s2;
    __syncthreads();
    for (int o = 128; o; o >>= 1) {
        if (threadIdx.x < o) {
            shm[threadIdx.x] += shm[threadIdx.x + o];
            shm[256 + threadIdx.x] += shm[256 + threadIdx.x + o];
        }
        __syncthreads();
    }
    if (threadIdx.x == 0) {
        float mu  = shm[0] * invN;
        float var = fmaf(-mu, mu, shm[256] * invN);
        float a = gg[c] * rsqrtf(var + EPSV);
        ab[c] = a;
        ab[CC + c] = fmaf(-mu, a, bb[c]);
    }
}

// ---------------- P = x @ Wq^T + fused fp16 cast of x --------------------------
__global__ void __launch_bounds__(256) p_gemm(
    const float* __restrict__ x, const float* __restrict__ Wq,
    float* __restrict__ P, __half2* __restrict__ xh)
{
    __shared__ float wqs[KK * C];
    __shared__ float red[8][KK * 32];
    for (int i = threadIdx.x; i < KK * C; i += 256) wqs[i] = Wq[i];
    __syncthreads();
    const int warp = threadIdx.x >> 5, lane = threadIdx.x & 31;
    const int row = blockIdx.x * 8 + warp;
    float4 xv = reinterpret_cast<const float4*>(x + (size_t)row * C)[lane];

    {
        const size_t base = (size_t)row * 64 + lane * 2;
        xh[base]     = __floats2half2_rn(xv.x, xv.y);
        xh[base + 1] = __floats2half2_rn(xv.z, xv.w);
    }

    float part[KK];
#pragma unroll
    for (int k = 0; k < KK; k++) {
        float4 w = reinterpret_cast<const float4*>(wqs + k * C)[lane];
        part[k] = xv.x * w.x + xv.y * w.y + xv.z * w.z + xv.w * w.w;
    }
#pragma unroll
    for (int k = 0; k < KK; k++) red[warp][lane * KK + k] = part[k];
    __syncwarp();
    if (lane < KK) {
        float s = 0.f;
#pragma unroll
        for (int j = 0; j < 32; j++) s += red[warp][j * KK + lane];
        P[(size_t)row * KK + lane] = s;
    }
}

// ---------------- vr = relu(bn(v)) as fp16 -------------------------------------
__global__ void __launch_bounds__(256) vrelu_kernel(
    const __half2* __restrict__ vh, const float* __restrict__ vab,
    __half2* __restrict__ vr, int n2)
{
    int i = blockIdx.x * 256 + threadIdx.x;
    if (i >= n2) return;
    int c2 = i & 127;
    float2 a = reinterpret_cast<const float2*>(vab)[c2];
    float2 b = reinterpret_cast<const float2*>(vab + CH)[c2];
    float2 v = __half22float2(vh[i]);
    vr[i] = __floats2half2_rn(fmaxf(fmaf(v.x, a.x, b.x), 0.f),
                              fmaxf(fmaf(v.y, a.y, b.y), 0.f));
}

// ---------------- q[n] = sum_k P[nbr[n,k], k] + stats -------------------------
__global__ void q_gather(const int* __restrict__ nbr, const float* __restrict__ P,
                         float* __restrict__ q, float* __restrict__ qpart)
{
    const int n = blockIdx.x * 256 + threadIdx.x;
    float s = 0.f;
#pragma unroll
    for (int k = 0; k < KK; k++) {
        int idx = nbr[(size_t)n * KK + k];
        s += P[(size_t)idx * KK + k];
    }
    q[n] = s;
    __shared__ float sh[512];
    sh[threadIdx.x] = s;
    sh[256 + threadIdx.x] = s * s;
    __syncthreads();
    for (int o = 128; o; o >>= 1) {
        if (threadIdx.x < o) {
            sh[threadIdx.x] += sh[threadIdx.x + o];
            sh[256 + threadIdx.x] += sh[256 + threadIdx.x + o];
        }
        __syncthreads();
    }
    if (threadIdx.x == 0) {
        qpart[blockIdx.x] = sh[0];
        qpart[NSB + blockIdx.x] = sh[256];
    }
}

__global__ void q_finalize(const float* __restrict__ qpart,
    const float* __restrict__ gq, const float* __restrict__ bq,
    float* __restrict__ qab, float invN)
{
    __shared__ float sh[2 * NSB];
    sh[threadIdx.x] = qpart[threadIdx.x];
    sh[NSB + threadIdx.x] = qpart[NSB + threadIdx.x];
    __syncthreads();
    for (int o = NSB / 2; o; o >>= 1) {
        if (threadIdx.x < o) {
            sh[threadIdx.x] += sh[threadIdx.x + o];
            sh[NSB + threadIdx.x] += sh[NSB + threadIdx.x + o];
        }
        __syncthreads();
    }
    if (threadIdx.x == 0) {
        float mu  = sh[0] * invN;
        float var = fmaf(-mu, mu, sh[NSB] * invN);
        float a = gq[0] * rsqrtf(var + EPSV);
        qab[0] = a;
        qab[1] = fmaf(-mu, a, bq[0]);
    }
}

// ---------------- choice = softmax( relu(bn(q))[nbr] @ ksum^T ) ---------------
__global__ void choice_kernel(const int* __restrict__ nbr, const float* __restrict__ q,
    const float* __restrict__ qab, const float* __restrict__ ks,
    float* __restrict__ choice)
{
    __shared__ float sks[2 * KK];
    if (threadIdx.x < 2 * KK) sks[threadIdx.x] = ks[threadIdx.x];
    __syncthreads();
    const int n = blockIdx.x * 256 + threadIdx.x;
    const float a = qab[0], b = qab[1];
    float l0 = 0.f, l1 = 0.f;
#pragma unroll
    for (int k = 0; k < KK; k++) {
        int idx = nbr[(size_t)n * KK + k];
        float qq = fmaxf(fmaf(q[idx], a, b), 0.f);
        l0 = fmaf(qq, sks[k], l0);
        l1 = fmaf(qq, sks[KK + k], l1);
    }
    float m = fmaxf(l0, l1);
    float e0 = expf(l0 - m), e1 = expf(l1 - m);
    float inv = 1.f / (e0 + e1);
    choice[(size_t)n * 2]     = e0 * inv;
    choice[(size_t)n * 2 + 1] = e1 * inv;
}

// ---------------- routed gather: fp16 codebook in smem, 7 blocks/SM ------------
constexpr int RG_ROWS = 16;
constexpr int RG_SMEM = 2 * KK * CH * 2 + (2 * RG_ROWS + KK * RG_ROWS) * 4;

__global__ void __launch_bounds__(256) routed_gather(
    const __half2* __restrict__ vr, const int* __restrict__ nbr,
    const float* __restrict__ choice, const __half* __restrict__ cbh,
    __half2* __restrict__ o1)
{
    extern __shared__ float sm[];
    __half* s_cb = reinterpret_cast<__half*>(sm);      // 2*27*256 halves
    float* s_ch = sm + (2 * KK * CH * 2) / 4;          // 2*16 floats
    int*   s_idx = (int*)(s_ch + 2 * RG_ROWS);         // 27*16 ints
    const int tid = threadIdx.x;
    const int grp = tid >> 6;        // 0..3 -> rows j*4+grp
    const int c4  = tid & 63;        // channel quad
    const int n0 = blockIdx.x * RG_ROWS;

    for (int i = tid; i < (2 * KK * CH * 2) / 16; i += 256)
        reinterpret_cast<float4*>(s_cb)[i] =
            reinterpret_cast<const float4*>(cbh)[i];
    if (tid < 2 * RG_ROWS) s_ch[tid] = choice[(size_t)n0 * 2 + tid];
    for (int i = tid; i < KK * RG_ROWS; i += 256) s_idx[i] = nbr[(size_t)n0 * KK + i];
    __syncthreads();

    const __half2* cb2 = reinterpret_cast<const __half2*>(s_cb);

    float4 acc0[4], acc1[4];
#pragma unroll
    for (int j = 0; j < 4; j++) {
        acc0[j] = make_float4(0.f, 0.f, 0.f, 0.f);
        acc1[j] = make_float4(0.f, 0.f, 0.f, 0.f);
    }

    for (int k = 0; k < KK; k++) {
        const int2 rw0 = *reinterpret_cast<const int2*>(cb2 + k * 128 + c4 * 2);
        const int2 rw1 = *reinterpret_cast<const int2*>(cb2 + (KK + k) * 128 + c4 * 2);
        const float2 w0a = __half22float2(*reinterpret_cast<const __half2*>(&rw0.x));
        const float2 w0b = __half22float2(*reinterpret_cast<const __half2*>(&rw0.y));
        const float2 w1a = __half22float2(*reinterpret_cast<const __half2*>(&rw1.x));
        const float2 w1b = __half22float2(*reinterpret_cast<const __half2*>(&rw1.y));
#pragma unroll
        for (int j = 0; j < 4; j++) {
            const int r = j * 4 + grp;
            const int idx = s_idx[r * KK + k];
            const int2 raw = __ldcg(reinterpret_cast<const int2*>(
                vr + (size_t)idx * 128 + c4 * 2));
            const float2 va = __half22float2(*reinterpret_cast<const __half2*>(&raw.x));
            const float2 vb = __half22float2(*reinterpret_cast<const __half2*>(&raw.y));
            acc0[j].x = fmaf(va.x, w0a.x, acc0[j].x);
            acc0[j].y = fmaf(va.y, w0a.y, acc0[j].y);
            acc0[j].z = fmaf(vb.x, w0b.x, acc0[j].z);
            acc0[j].w = fmaf(vb.y, w0b.y, acc0[j].w);
            acc1[j].x = fmaf(va.x, w1a.x, acc1[j].x);
            acc1[j].y = fmaf(va.y, w1a.y, acc1[j].y);
            acc1[j].z = fmaf(vb.x, w1b.x, acc1[j].z);
            acc1[j].w = fmaf(vb.y, w1b.y, acc1[j].w);
        }
    }
#pragma unroll
    for (int j = 0; j < 4; j++) {
        const int r = j * 4 + grp;
        const float c0 = s_ch[2 * r], c1 = s_ch[2 * r + 1];
        float o0 = fmaf(c0, acc0[j].x, c1 * acc1[j].x);
        float o1v = fmaf(c0, acc0[j].y, c1 * acc1[j].y);
        float o2 = fmaf(c0, acc0[j].z, c1 * acc1[j].z);
        float o3 = fmaf(c0, acc0[j].w, c1 * acc1[j].w);
        const size_t base = (size_t)(n0 + r) * 128 + c4 * 2;
        o1[base]     = __floats2half2_rn(o0, o1v);
        o1[base + 1] = __floats2half2_rn(o2, o3);
    }
}

// ---------------- final: relu(bn(y)) + x, float4 vectorized ---------------------
__global__ void __launch_bounds__(256) final_kernel(
    const float4* __restrict__ y, const float4* __restrict__ x,
    const float* __restrict__ yab, float4* __restrict__ out)
{
    const int i = blockIdx.x * 256 + threadIdx.x;
    const int c4 = i & 31;
    const float4 a = reinterpret_cast<const float4*>(yab)[c4];
    const float4 b = reinterpret_cast<const float4*>(yab + C)[c4];
    const float4 yv = y[i];
    const float4 xv = x[i];
    float4 o;
    o.x = fmaxf(fmaf(yv.x, a.x, b.x), 0.f) + xv.x;
    o.y = fmaxf(fmaf(yv.y, a.y, b.y), 0.f) + xv.y;
    o.z = fmaxf(fmaf(yv.z, a.z, b.z), 0.f) + xv.z;
    o.w = fmaxf(fmaf(yv.w, a.w, b.w), 0.f) + xv.w;
    out[i] = o;
}

// ---------------- launch -------------------------------------------------------
extern "C" void kernel_launch(void* const* d_in, const int* in_sizes, int n_in,
                              void* d_out, int out_size)
{
    const float* x    = (const float*)d_in[0];
    const int*   nbr  = (const int*)  d_in[1];
    const float* Wv   = (const float*)d_in[2];
    const float* gv   = (const float*)d_in[3];
    const float* bv   = (const float*)d_in[4];
    const float* Wq   = (const float*)d_in[5];
    const float* gq   = (const float*)d_in[6];
    const float* bq   = (const float*)d_in[7];
    const float* cb   = (const float*)d_in[8];
    const float* Wout = (const float*)d_in[9];
    const float* go   = (const float*)d_in[10];
    const float* bo   = (const float*)d_in[11];
    float* out = (float*)d_out;
    const int N = in_sizes[0] / C;

    __half *pvh, *pvr, *pxh, *po1, *pWvh, *pWoh, *pcbh;
    float *pP, *pq, *py, *ppart, *pqpart, *pvab, *pqab, *pyab, *pksum, *pchoice;
    cudaGetSymbolAddress((void**)&pvh,    g_vh);
    cudaGetSymbolAddress((void**)&pvr,    g_vr);
    cudaGetSymbolAddress((void**)&pxh,    g_xh);
    cudaGetSymbolAddress((void**)&po1,    g_o1);
    cudaGetSymbolAddress((void**)&pWvh,   g_Wvh);
    cudaGetSymbolAddress((void**)&pWoh,   g_Woh);
    cudaGetSymbolAddress((void**)&pcbh,   g_cbh);
    cudaGetSymbolAddress((void**)&pP,     g_P);
    cudaGetSymbolAddress((void**)&pq,     g_q);
    cudaGetSymbolAddress((void**)&py,     g_y);
    cudaGetSymbolAddress((void**)&ppart,  g_part);
    cudaGetSymbolAddress((void**)&pqpart, g_qpart);
    cudaGetSymbolAddress((void**)&pvab,   g_vab);
    cudaGetSymbolAddress((void**)&pqab,   g_qab);
    cudaGetSymbolAddress((void**)&pyab,   g_yab);
    cudaGetSymbolAddress((void**)&pksum,  g_ksum);
    cudaGetSymbolAddress((void**)&pchoice,g_choice);

    cudaFuncSetAttribute(routed_gather,
                         cudaFuncAttributeMaxDynamicSharedMemorySize, RG_SMEM);
    cudaFuncSetAttribute((hgemm16<128, true>),
                         cudaFuncAttributeMaxDynamicSharedMemorySize, HG_SMEM);
    cudaFuncSetAttribute((hgemm16<256, false>),
                         cudaFuncAttributeMaxDynamicSharedMemorySize, HG_SMEM);

    const float invN = 1.f / (float)N;

    // weight fp16 casts + ksum + fp16 codebook (one kernel)
    prep_kernel<<<64 + MM * KK, 256>>>(Wv, Wout, cb,
        (__half2*)pWvh, (__half2*)pWoh, pksum, pcbh);
    // P = x @ Wq^T, also emits x as fp16
    p_gemm<<<N / 8, 256>>>(x, Wq, pP, (__half2*)pxh);
    // v = x @ Wv  (plain fp16 GEMM, fp16 out, fused column stats)
    hgemm16<128, true><<<dim3(N / 128, CH / 128), 256, HG_SMEM>>>(
        pxh, pWvh, pvh, CH, ppart);
    reduce_affine<<<CH, 256>>>(ppart, gv, bv, pvab, invN, N / 128, CH);
    // vr = relu(bn(v)) fp16
    {
        const int n2 = N * CH / 2;
        vrelu_kernel<<<n2 / 256, 256>>>(
            (const __half2*)pvh, pvab, (__half2*)pvr, n2);
    }
    // q pipeline
    q_gather<<<N / 256, 256>>>(nbr, pP, pq, pqpart);
    q_finalize<<<1, NSB>>>(pqpart, gq, bq, pqab, invN);
    choice_kernel<<<N / 256, 256>>>(nbr, pq, pqab, pksum, pchoice);
    // routed channelwise gather conv (fp16 codebook, 7 blocks/SM) -> fp16 out1
    routed_gather<<<N / RG_ROWS, 256, RG_SMEM>>>(
        (const __half2*)pvr, nbr, pchoice, pcbh, (__half2*)po1);
    // y = out1 @ Wout (plain fp16 GEMM, fp32 out, fused stats)
    hgemm16<256, false><<<dim3(N / 128, 1), 256, HG_SMEM>>>(
        po1, pWoh, py, C, ppart);
    reduce_affine<<<C, 256>>>(ppart, go, bo, pyab, invN, N / 128, C);
    // out = relu(bn(y)) + x (float4 vectorized)
    final_kernel<<<(size_t)N * C / 4 / 256, 256>>>(
        (const float4*)py, (const float4*)x, pyab, (float4*)out);
}